// round 1
// baseline (speedup 1.0000x reference)
#include <cuda_runtime.h>
#include <cstdint>

#define NN   1024      // nodes
#define EE   2048      // raw edges
#define ET   3072      // edges + self loops
#define HH   32        // heads
#define CMX  1028      // max per-head channel dim

// ---------------- scratch (device globals; no allocation allowed) ----------------
__device__ float    g_xl[(size_t)NN * HH * CMX];   // 134.7 MB
__device__ float    g_xr[(size_t)NN * HH * CMX];   // 134.7 MB
__device__ float    g_buf1[NN * CMX];
__device__ float    g_buf2[NN * CMX];
__device__ float    g_score[ET * HH];
__device__ float    g_alpha[ET * HH];
__device__ unsigned g_smax[NN * HH];
__device__ float    g_denom[NN * HH];
__device__ int      g_src[ET];
__device__ int      g_dst[ET];
__device__ int      g_is64;

// ---------------- helpers ----------------
__device__ __forceinline__ unsigned flipf(float f) {
    unsigned u = __float_as_uint(f);
    return u ^ ((unsigned)((int)u >> 31) | 0x80000000u);
}
__device__ __forceinline__ float unflipf(unsigned v) {
    unsigned m = (v & 0x80000000u) ? 0x80000000u : 0xFFFFFFFFu;
    return __uint_as_float(v ^ m);
}

// ---------------- edge dtype detection + edge build ----------------
__global__ void detect_dtype_kernel(const void* ei) {
    __shared__ int bad;
    if (threadIdx.x == 0) bad = 0;
    __syncthreads();
    const long long* p = (const long long*)ei;
    // Read only the first EE int64 slots (= full buffer if it is int32).
    for (int i = threadIdx.x; i < EE; i += blockDim.x) {
        long long v = p[i];
        if (v < 0 || v >= NN) bad = 1;
    }
    __syncthreads();
    if (threadIdx.x == 0) g_is64 = !bad;
}

__global__ void build_edges_kernel(const void* ei) {
    int e = blockIdx.x * blockDim.x + threadIdx.x;
    if (e >= ET) return;
    if (e < EE) {
        if (g_is64) {
            const long long* p = (const long long*)ei;
            g_src[e] = (int)p[e];
            g_dst[e] = (int)p[EE + e];
        } else {
            const int* p = (const int*)ei;
            g_src[e] = p[e];
            g_dst[e] = p[EE + e];
        }
    } else {
        g_src[e] = e - EE;
        g_dst[e] = e - EE;
    }
}

// ---------------- SGEMM: C[M,Nn] = A[M,K] @ B[K,Nn] + bias, optional leakyrelu ----------------
// BM=BN=128, BK=8, 256 threads, 8x8 per thread, interleaved register tiles (conflict-free LDS).
__global__ void sgemm_kernel(const float* __restrict__ A, const float* __restrict__ B,
                             const float* __restrict__ bias, float* __restrict__ C,
                             int M, int Nn, int K, int act) {
    __shared__ float As[8][128];
    __shared__ float Bs[8][128];
    const int bx = blockIdx.x * 128;
    const int by = blockIdx.y * 128;
    const int tid = threadIdx.x;
    const int tr = tid / 16;        // 0..15
    const int tc = tid % 16;        // 0..15

    float acc[8][8];
#pragma unroll
    for (int i = 0; i < 8; i++)
#pragma unroll
        for (int j = 0; j < 8; j++) acc[i][j] = 0.f;

    const int row_a = tid / 2;          // 0..127
    const int cola0 = (tid % 2) * 4;    // 0 or 4
    const int row_b = tid / 32;         // 0..7
    const int colb0 = (tid % 32) * 4;   // 0..124

    for (int k0 = 0; k0 < K; k0 += 8) {
#pragma unroll
        for (int i = 0; i < 4; i++) {
            int r = by + row_a;
            int kk = k0 + cola0 + i;
            As[cola0 + i][row_a] = (r < M && kk < K) ? A[(size_t)r * K + kk] : 0.f;
        }
#pragma unroll
        for (int i = 0; i < 4; i++) {
            int kk = k0 + row_b;
            int c = bx + colb0 + i;
            Bs[row_b][colb0 + i] = (kk < K && c < Nn) ? B[(size_t)kk * Nn + c] : 0.f;
        }
        __syncthreads();
#pragma unroll
        for (int kk = 0; kk < 8; kk++) {
            float a[8], b[8];
#pragma unroll
            for (int i = 0; i < 8; i++) a[i] = As[kk][tr + 16 * i];
#pragma unroll
            for (int j = 0; j < 8; j++) b[j] = Bs[kk][tc + 16 * j];
#pragma unroll
            for (int i = 0; i < 8; i++)
#pragma unroll
                for (int j = 0; j < 8; j++) acc[i][j] += a[i] * b[j];
        }
        __syncthreads();
    }

#pragma unroll
    for (int i = 0; i < 8; i++) {
        int r = by + tr + 16 * i;
        if (r >= M) continue;
#pragma unroll
        for (int j = 0; j < 8; j++) {
            int c = bx + tc + 16 * j;
            if (c >= Nn) continue;
            float v = acc[i][j] + bias[c];
            if (act) v = (v > 0.f) ? v : 0.01f * v;
            C[(size_t)r * Nn + c] = v;
        }
    }
}

// ---------------- softmax state init ----------------
__global__ void init_soft_kernel() {
    int i = blockIdx.x * blockDim.x + threadIdx.x;
    if (i < NN * HH) {
        g_smax[i] = 0u;       // encoded: below -inf
        g_denom[i] = 0.f;
    }
}

// ---------------- per-(edge,head) attention score: one warp each ----------------
__global__ void score_kernel(const float* __restrict__ att, int C) {
    int gw = (blockIdx.x * blockDim.x + threadIdx.x) >> 5;
    int lane = threadIdx.x & 31;
    if (gw >= ET * HH) return;
    int e = gw / HH, h = gw % HH;
    int s = g_src[e], d = g_dst[e];
    const float* xl = g_xl + ((size_t)s * HH + h) * C;
    const float* xr = g_xr + ((size_t)d * HH + h) * C;
    const float* at = att + h * C;
    float acc = 0.f;
    for (int c = lane; c < C; c += 32) {
        float v = xl[c] + xr[c];
        v = (v > 0.f) ? v : 0.2f * v;
        acc += at[c] * v;
    }
#pragma unroll
    for (int o = 16; o; o >>= 1) acc += __shfl_xor_sync(0xffffffffu, acc, o);
    if (lane == 0) {
        g_score[e * HH + h] = acc;
        atomicMax(&g_smax[d * HH + h], flipf(acc));
    }
}

// ---------------- alpha = exp(score - max); accumulate denominators ----------------
__global__ void alpha_kernel() {
    int i = blockIdx.x * blockDim.x + threadIdx.x;
    if (i >= ET * HH) return;
    int e = i / HH, h = i % HH;
    int d = g_dst[e];
    float m = unflipf(g_smax[d * HH + h]);
    float a = expf(g_score[i] - m);
    g_alpha[i] = a;
    atomicAdd(&g_denom[d * HH + h], a);
}

// ---------------- out init with bias ----------------
__global__ void init_out_kernel(float* __restrict__ out, const float* __restrict__ bias, int C) {
    int i = blockIdx.x * blockDim.x + threadIdx.x;
    if (i < NN * C) out[i] = bias[i % C];
}

// ---------------- aggregation: one block per edge ----------------
__global__ void aggregate_kernel(float* __restrict__ out, int C) {
    int e = blockIdx.x;
    __shared__ float a[HH];
    int d = g_dst[e], s = g_src[e];
    if (threadIdx.x < HH) {
        int h = threadIdx.x;
        a[h] = g_alpha[e * HH + h] / g_denom[d * HH + h] * (1.0f / HH);
    }
    __syncthreads();
    const float* xl = g_xl + (size_t)s * HH * C;
    float* o = out + (size_t)d * C;
    for (int c = threadIdx.x; c < C; c += blockDim.x) {
        float acc = 0.f;
#pragma unroll 8
        for (int h = 0; h < HH; h++) acc += a[h] * xl[(size_t)h * C + c];
        atomicAdd(&o[c], acc);
    }
}

// ---------------- elementwise leaky relu (0.01) ----------------
__global__ void lrelu_kernel(float* __restrict__ z, int n) {
    int i = blockIdx.x * blockDim.x + threadIdx.x;
    if (i < n) {
        float v = z[i];
        z[i] = (v > 0.f) ? v : 0.01f * v;
    }
}

// ---------------- host-side orchestration ----------------
static void run_gemm(const float* A, const float* B, const float* bias, float* C,
                     int M, int Nn, int K, int act) {
    dim3 grid((Nn + 127) / 128, (M + 127) / 128);
    sgemm_kernel<<<grid, 256>>>(A, B, bias, C, M, Nn, K, act);
}

static void gat_layer(const float* zin, int Cin, int Cout,
                      const float* wl, const float* bl,
                      const float* wr, const float* br,
                      const float* att, const float* gb,
                      float* xl, float* xr, float* zout, int act_after) {
    int HC = HH * Cout;
    run_gemm(zin, wl, bl, xl, NN, HC, Cin, 0);
    run_gemm(zin, wr, br, xr, NN, HC, Cin, 0);
    init_soft_kernel<<<(NN * HH + 255) / 256, 256>>>();
    score_kernel<<<(ET * HH) / 8, 256>>>(att, Cout);   // 8 warps per block
    alpha_kernel<<<(ET * HH + 255) / 256, 256>>>();
    init_out_kernel<<<(NN * Cout + 255) / 256, 256>>>(zout, gb, Cout);
    aggregate_kernel<<<ET, 256>>>(zout, Cout);
    if (act_after)
        lrelu_kernel<<<(NN * Cout + 255) / 256, 256>>>(zout, NN * Cout);
}

extern "C" void kernel_launch(void* const* d_in, const int* in_sizes, int n_in,
                              void* d_out, int out_size) {
    const float* x  = (const float*)d_in[0];
    const void*  ei = d_in[1];
    const float* w1l = (const float*)d_in[2];
    const float* b1l = (const float*)d_in[3];
    const float* w1r = (const float*)d_in[4];
    const float* b1r = (const float*)d_in[5];
    const float* att1 = (const float*)d_in[6];
    const float* gb1  = (const float*)d_in[7];
    const float* w2l = (const float*)d_in[8];
    const float* b2l = (const float*)d_in[9];
    const float* w2r = (const float*)d_in[10];
    const float* b2r = (const float*)d_in[11];
    const float* att2 = (const float*)d_in[12];
    const float* gb2  = (const float*)d_in[13];
    const float* w3l = (const float*)d_in[14];
    const float* b3l = (const float*)d_in[15];
    const float* w3r = (const float*)d_in[16];
    const float* b3r = (const float*)d_in[17];
    const float* att3 = (const float*)d_in[18];
    const float* gb3  = (const float*)d_in[19];
    const float* dw1 = (const float*)d_in[20];
    const float* db1 = (const float*)d_in[21];
    const float* dw2 = (const float*)d_in[22];
    const float* db2 = (const float*)d_in[23];
    const float* dw3 = (const float*)d_in[24];
    const float* db3 = (const float*)d_in[25];

    void* p;
    cudaGetSymbolAddress(&p, g_xl);   float* xl   = (float*)p;
    cudaGetSymbolAddress(&p, g_xr);   float* xr   = (float*)p;
    cudaGetSymbolAddress(&p, g_buf1); float* buf1 = (float*)p;
    cudaGetSymbolAddress(&p, g_buf2); float* buf2 = (float*)p;

    // edges (dtype-robust: int64 vs int32)
    detect_dtype_kernel<<<1, 256>>>(ei);
    build_edges_kernel<<<(ET + 255) / 256, 256>>>(ei);

    // GATv2 stack
    gat_layer(x,    4,    128,  w1l, b1l, w1r, b1r, att1, gb1, xl, xr, buf1, 1);
    gat_layer(buf1, 128,  512,  w2l, b2l, w2r, b2r, att2, gb2, xl, xr, buf2, 1);
    gat_layer(buf2, 512,  1028, w3l, b3l, w3r, b3r, att3, gb3, xl, xr, buf1, 0);

    // decoder MLP
    run_gemm(buf1, dw1, db1, buf2, NN, 512, 1028, 1);
    run_gemm(buf2, dw2, db2, buf1, NN, 128, 512, 1);
    run_gemm(buf1, dw3, db3, (float*)d_out, NN, 2, 128, 0);

    (void)in_sizes; (void)n_in; (void)out_size;
}

// round 2
// speedup vs baseline: 2.5154x; 2.5154x over previous
#include <cuda_runtime.h>
#include <cuda_bf16.h>
#include <cstdint>

#define NN   1024      // nodes
#define EE   2048      // raw edges
#define ET   3072      // edges + self loops
#define HH   32        // heads
#define CMX  1028      // max per-head channel dim
#define KPMX 1056      // max padded K
#define BMAX 16842752  // 512*32896 max weight elements

// ---------------- scratch (device globals; no allocation allowed) ----------------
__device__ float         g_xl[(size_t)NN * HH * CMX];
__device__ float         g_xr[(size_t)NN * HH * CMX];
__device__ float         g_buf1[NN * CMX];
__device__ float         g_buf2[NN * CMX];
__device__ float         g_score[ET * HH];
__device__ float         g_alpha[ET * HH];
__device__ unsigned      g_smax[NN * HH];
__device__ float         g_denom[NN * HH];
__device__ int           g_src[ET];
__device__ int           g_dst[ET];
__device__ int           g_is64;
__device__ __nv_bfloat16 g_ah[NN * KPMX];
__device__ __nv_bfloat16 g_al[NN * KPMX];
__device__ __nv_bfloat16 g_bh[BMAX];
__device__ __nv_bfloat16 g_bl[BMAX];

// ---------------- helpers ----------------
__device__ __forceinline__ unsigned flipf(float f) {
    unsigned u = __float_as_uint(f);
    return u ^ ((unsigned)((int)u >> 31) | 0x80000000u);
}
__device__ __forceinline__ float unflipf(unsigned v) {
    unsigned m = (v & 0x80000000u) ? 0x80000000u : 0xFFFFFFFFu;
    return __uint_as_float(v ^ m);
}

// ---------------- edge dtype detection + edge build ----------------
__global__ void detect_dtype_kernel(const void* ei) {
    __shared__ int bad;
    if (threadIdx.x == 0) bad = 0;
    __syncthreads();
    const long long* p = (const long long*)ei;
    for (int i = threadIdx.x; i < EE; i += blockDim.x) {
        long long v = p[i];
        if (v < 0 || v >= NN) bad = 1;
    }
    __syncthreads();
    if (threadIdx.x == 0) g_is64 = !bad;
}

__global__ void build_edges_kernel(const void* ei) {
    int e = blockIdx.x * blockDim.x + threadIdx.x;
    if (e >= ET) return;
    if (e < EE) {
        if (g_is64) {
            const long long* p = (const long long*)ei;
            g_src[e] = (int)p[e];
            g_dst[e] = (int)p[EE + e];
        } else {
            const int* p = (const int*)ei;
            g_src[e] = p[e];
            g_dst[e] = p[EE + e];
        }
    } else {
        g_src[e] = e - EE;
        g_dst[e] = e - EE;
    }
}

// ---------------- fp32 -> bf16 hi/lo split with zero padding ----------------
__global__ void convert_pad_kernel(const float* __restrict__ src,
                                   __nv_bfloat16* __restrict__ hi,
                                   __nv_bfloat16* __restrict__ lo,
                                   int R, int Cc, int Rout, int Cout) {
    int i = blockIdx.x * blockDim.x + threadIdx.x;
    if (i >= Rout * Cout) return;
    int r = i / Cout, c = i - r * Cout;
    float v = (r < R && c < Cc) ? src[(size_t)r * Cc + c] : 0.f;
    __nv_bfloat16 h = __float2bfloat16(v);
    hi[i] = h;
    lo[i] = __float2bfloat16(v - __bfloat162float(h));
}

// ---------------- tensor-core GEMM (bf16x3 split, fp32 accum) ----------------
// C[M,Nn] = A[M,Kp] @ B[Kp,Nn] + bias, optional leakyrelu(0.01).
// Requires M%128==0, Nn%128==0, Kp%32==0. BM=BN=128, BK=32, 256 threads.
#define ASTR 40    // padded row stride (bf16) for A tile [128][32]
#define BSTR 136   // padded row stride (bf16) for B tile [32][128]

#define LDMX4(R0,R1,R2,R3,ADDR) \
    asm volatile("ldmatrix.sync.aligned.m8n8.x4.shared.b16 {%0,%1,%2,%3}, [%4];" \
        : "=r"(R0), "=r"(R1), "=r"(R2), "=r"(R3) : "r"(ADDR))
#define LDMX2T(R0,R1,ADDR) \
    asm volatile("ldmatrix.sync.aligned.m8n8.x2.trans.shared.b16 {%0,%1}, [%2];" \
        : "=r"(R0), "=r"(R1) : "r"(ADDR))
#define MMA16816(C0,C1,C2,C3,A0,A1,A2,A3,B0,B1) \
    asm volatile("mma.sync.aligned.m16n8k16.row.col.f32.bf16.bf16.f32 " \
        "{%0,%1,%2,%3}, {%4,%5,%6,%7}, {%8,%9}, {%0,%1,%2,%3};" \
        : "+f"(C0), "+f"(C1), "+f"(C2), "+f"(C3) \
        : "r"(A0), "r"(A1), "r"(A2), "r"(A3), "r"(B0), "r"(B1))

__global__ __launch_bounds__(256) void tc_gemm_kernel(
    const __nv_bfloat16* __restrict__ Ah, const __nv_bfloat16* __restrict__ Al,
    const __nv_bfloat16* __restrict__ Bh, const __nv_bfloat16* __restrict__ Bl,
    const float* __restrict__ bias, float* __restrict__ C,
    int M, int Nn, int Kp, int act)
{
    __shared__ __nv_bfloat16 sAh[128 * ASTR];
    __shared__ __nv_bfloat16 sAl[128 * ASTR];
    __shared__ __nv_bfloat16 sBh[32 * BSTR];
    __shared__ __nv_bfloat16 sBl[32 * BSTR];

    const int tid  = threadIdx.x;
    const int warp = tid >> 5;
    const int lane = tid & 31;
    const int wm = (warp >> 2) * 64;    // 0 or 64
    const int wn = (warp & 3) * 32;     // 0,32,64,96
    const int bx = blockIdx.x * 128;
    const int by = blockIdx.y * 128;

    float acc[4][4][4];
#pragma unroll
    for (int mi = 0; mi < 4; mi++)
#pragma unroll
        for (int ni = 0; ni < 4; ni++)
#pragma unroll
            for (int k = 0; k < 4; k++) acc[mi][ni][k] = 0.f;

    uint32_t sAh_base, sAl_base, sBh_base, sBl_base;
    sAh_base = (uint32_t)__cvta_generic_to_shared(sAh);
    sAl_base = (uint32_t)__cvta_generic_to_shared(sAl);
    sBh_base = (uint32_t)__cvta_generic_to_shared(sBh);
    sBl_base = (uint32_t)__cvta_generic_to_shared(sBl);

    const int r8 = lane & 7;            // ldmatrix row within 8x8
    const int gA = lane >> 3;           // 0..3
    const int gB = (lane >> 3) & 1;     // 0..1

    for (int k0 = 0; k0 < Kp; k0 += 32) {
        __syncthreads();
        // load A tiles: 128x32 bf16 per array, uint4 (8 bf16) per transfer
#pragma unroll
        for (int l = 0; l < 2; l++) {
            int idx = tid + l * 256;
            int row = idx >> 2, seg = idx & 3;
            size_t go = (size_t)(by + row) * Kp + k0 + seg * 8;
            int so = row * ASTR + seg * 8;
            *(uint4*)&sAh[so] = *(const uint4*)&Ah[go];
            *(uint4*)&sAl[so] = *(const uint4*)&Al[go];
        }
        // load B tiles: 32x128
#pragma unroll
        for (int l = 0; l < 2; l++) {
            int idx = tid + l * 256;
            int row = idx >> 4, seg = idx & 15;
            size_t go = (size_t)(k0 + row) * Nn + bx + seg * 8;
            int so = row * BSTR + seg * 8;
            *(uint4*)&sBh[so] = *(const uint4*)&Bh[go];
            *(uint4*)&sBl[so] = *(const uint4*)&Bl[go];
        }
        __syncthreads();

#pragma unroll
        for (int ks = 0; ks < 2; ks++) {
            const int ko = ks * 16;
            uint32_t ah[4][4], al[4][4], bh[4][2], bl[4][2];
#pragma unroll
            for (int mi = 0; mi < 4; mi++) {
                int row = wm + mi * 16 + r8 + (gA & 1) * 8;
                int col = ko + (gA >> 1) * 8;
                uint32_t off = (uint32_t)(row * ASTR + col) * 2;
                LDMX4(ah[mi][0], ah[mi][1], ah[mi][2], ah[mi][3], sAh_base + off);
                LDMX4(al[mi][0], al[mi][1], al[mi][2], al[mi][3], sAl_base + off);
            }
#pragma unroll
            for (int ni = 0; ni < 4; ni++) {
                int row = ko + gB * 8 + r8;
                int col = wn + ni * 8;
                uint32_t off = (uint32_t)(row * BSTR + col) * 2;
                LDMX2T(bh[ni][0], bh[ni][1], sBh_base + off);
                LDMX2T(bl[ni][0], bl[ni][1], sBl_base + off);
            }
#pragma unroll
            for (int mi = 0; mi < 4; mi++) {
#pragma unroll
                for (int ni = 0; ni < 4; ni++) {
                    float* c = acc[mi][ni];
                    MMA16816(c[0], c[1], c[2], c[3],
                             ah[mi][0], ah[mi][1], ah[mi][2], ah[mi][3],
                             bh[ni][0], bh[ni][1]);
                    MMA16816(c[0], c[1], c[2], c[3],
                             ah[mi][0], ah[mi][1], ah[mi][2], ah[mi][3],
                             bl[ni][0], bl[ni][1]);
                    MMA16816(c[0], c[1], c[2], c[3],
                             al[mi][0], al[mi][1], al[mi][2], al[mi][3],
                             bh[ni][0], bh[ni][1]);
                }
            }
        }
    }

    // epilogue
    const int g = lane >> 2, tig = lane & 3;
#pragma unroll
    for (int mi = 0; mi < 4; mi++) {
#pragma unroll
        for (int ni = 0; ni < 4; ni++) {
            int row = by + wm + mi * 16 + g;
            int col = bx + wn + ni * 8 + tig * 2;
            float bv0 = bias[col], bv1 = bias[col + 1];
            float v0 = acc[mi][ni][0] + bv0;
            float v1 = acc[mi][ni][1] + bv1;
            float v2 = acc[mi][ni][2] + bv0;
            float v3 = acc[mi][ni][3] + bv1;
            if (act) {
                v0 = (v0 > 0.f) ? v0 : 0.01f * v0;
                v1 = (v1 > 0.f) ? v1 : 0.01f * v1;
                v2 = (v2 > 0.f) ? v2 : 0.01f * v2;
                v3 = (v3 > 0.f) ? v3 : 0.01f * v3;
            }
            C[(size_t)row * Nn + col]           = v0;
            C[(size_t)row * Nn + col + 1]       = v1;
            C[(size_t)(row + 8) * Nn + col]     = v2;
            C[(size_t)(row + 8) * Nn + col + 1] = v3;
        }
    }
}

// ---------------- fp32 SGEMM (small shapes: K=4 layer-1, final N=2) ----------------
__global__ void sgemm_kernel(const float* __restrict__ A, const float* __restrict__ B,
                             const float* __restrict__ bias, float* __restrict__ C,
                             int M, int Nn, int K, int act) {
    __shared__ float As[8][128];
    __shared__ float Bs[8][128];
    const int bx = blockIdx.x * 128;
    const int by = blockIdx.y * 128;
    const int tid = threadIdx.x;
    const int tr = tid / 16;
    const int tc = tid % 16;

    float acc[8][8];
#pragma unroll
    for (int i = 0; i < 8; i++)
#pragma unroll
        for (int j = 0; j < 8; j++) acc[i][j] = 0.f;

    const int row_a = tid / 2;
    const int cola0 = (tid % 2) * 4;
    const int row_b = tid / 32;
    const int colb0 = (tid % 32) * 4;

    for (int k0 = 0; k0 < K; k0 += 8) {
#pragma unroll
        for (int i = 0; i < 4; i++) {
            int r = by + row_a;
            int kk = k0 + cola0 + i;
            As[cola0 + i][row_a] = (r < M && kk < K) ? A[(size_t)r * K + kk] : 0.f;
        }
#pragma unroll
        for (int i = 0; i < 4; i++) {
            int kk = k0 + row_b;
            int c = bx + colb0 + i;
            Bs[row_b][colb0 + i] = (kk < K && c < Nn) ? B[(size_t)kk * Nn + c] : 0.f;
        }
        __syncthreads();
#pragma unroll
        for (int kk = 0; kk < 8; kk++) {
            float a[8], b[8];
#pragma unroll
            for (int i = 0; i < 8; i++) a[i] = As[kk][tr + 16 * i];
#pragma unroll
            for (int j = 0; j < 8; j++) b[j] = Bs[kk][tc + 16 * j];
#pragma unroll
            for (int i = 0; i < 8; i++)
#pragma unroll
                for (int j = 0; j < 8; j++) acc[i][j] += a[i] * b[j];
        }
        __syncthreads();
    }

#pragma unroll
    for (int i = 0; i < 8; i++) {
        int r = by + tr + 16 * i;
        if (r >= M) continue;
#pragma unroll
        for (int j = 0; j < 8; j++) {
            int c = bx + tc + 16 * j;
            if (c >= Nn) continue;
            float v = acc[i][j] + bias[c];
            if (act) v = (v > 0.f) ? v : 0.01f * v;
            C[(size_t)r * Nn + c] = v;
        }
    }
}

// ---------------- softmax state init ----------------
__global__ void init_soft_kernel() {
    int i = blockIdx.x * blockDim.x + threadIdx.x;
    if (i < NN * HH) {
        g_smax[i] = 0u;
        g_denom[i] = 0.f;
    }
}

// ---------------- per-(edge,head) attention score: one warp each ----------------
__global__ void score_kernel(const float* __restrict__ att, int C) {
    int gw = (blockIdx.x * blockDim.x + threadIdx.x) >> 5;
    int lane = threadIdx.x & 31;
    if (gw >= ET * HH) return;
    int e = gw / HH, h = gw % HH;
    int s = g_src[e], d = g_dst[e];
    const float* xl = g_xl + ((size_t)s * HH + h) * C;
    const float* xr = g_xr + ((size_t)d * HH + h) * C;
    const float* at = att + h * C;
    float acc = 0.f;
    for (int c = lane; c < C; c += 32) {
        float v = xl[c] + xr[c];
        v = (v > 0.f) ? v : 0.2f * v;
        acc += at[c] * v;
    }
#pragma unroll
    for (int o = 16; o; o >>= 1) acc += __shfl_xor_sync(0xffffffffu, acc, o);
    if (lane == 0) {
        g_score[e * HH + h] = acc;
        atomicMax(&g_smax[d * HH + h], flipf(acc));
    }
}

// ---------------- alpha = exp(score - max); accumulate denominators ----------------
__global__ void alpha_kernel() {
    int i = blockIdx.x * blockDim.x + threadIdx.x;
    if (i >= ET * HH) return;
    int e = i / HH, h = i % HH;
    int d = g_dst[e];
    float m = unflipf(g_smax[d * HH + h]);
    float a = expf(g_score[i] - m);
    g_alpha[i] = a;
    atomicAdd(&g_denom[d * HH + h], a);
}

// ---------------- out init with bias ----------------
__global__ void init_out_kernel(float* __restrict__ out, const float* __restrict__ bias, int C) {
    int i = blockIdx.x * blockDim.x + threadIdx.x;
    if (i < NN * C) out[i] = bias[i % C];
}

// ---------------- aggregation: one block per edge ----------------
__global__ void aggregate_kernel(float* __restrict__ out, int C) {
    int e = blockIdx.x;
    __shared__ float a[HH];
    int d = g_dst[e], s = g_src[e];
    if (threadIdx.x < HH) {
        int h = threadIdx.x;
        a[h] = g_alpha[e * HH + h] / g_denom[d * HH + h] * (1.0f / HH);
    }
    __syncthreads();
    const float* xl = g_xl + (size_t)s * HH * C;
    float* o = out + (size_t)d * C;
    for (int c = threadIdx.x; c < C; c += blockDim.x) {
        float acc = 0.f;
#pragma unroll 8
        for (int h = 0; h < HH; h++) acc += a[h] * xl[(size_t)h * C + c];
        atomicAdd(&o[c], acc);
    }
}

// ---------------- elementwise leaky relu (0.01) ----------------
__global__ void lrelu_kernel(float* __restrict__ z, int n) {
    int i = blockIdx.x * blockDim.x + threadIdx.x;
    if (i < n) {
        float v = z[i];
        z[i] = (v > 0.f) ? v : 0.01f * v;
    }
}

// ---------------- host-side orchestration ----------------
static float* s_ah; static float* s_dummy;
static __nv_bfloat16 *h_ah, *h_al, *h_bh, *h_bl;

static void run_sgemm(const float* A, const float* B, const float* bias, float* C,
                      int M, int Nn, int K, int act) {
    dim3 grid((Nn + 127) / 128, (M + 127) / 128);
    sgemm_kernel<<<grid, 256>>>(A, B, bias, C, M, Nn, K, act);
}

static void convert_A(const float* A, int M, int K, int Kp) {
    int n = M * Kp;
    convert_pad_kernel<<<(n + 255) / 256, 256>>>(A, h_ah, h_al, M, K, M, Kp);
}

static void run_tc_gemm(const float* B, const float* bias, float* C,
                        int M, int Nn, int K, int Kp, int act) {
    int n = Kp * Nn;
    convert_pad_kernel<<<(n + 255) / 256, 256>>>(B, h_bh, h_bl, K, Nn, Kp, Nn);
    dim3 grid(Nn / 128, M / 128);
    tc_gemm_kernel<<<grid, 256>>>(h_ah, h_al, h_bh, h_bl, bias, C, M, Nn, Kp, act);
}

static void gat_attention(const float* att, const float* gb, float* zout,
                          int Cout, int act_after) {
    init_soft_kernel<<<(NN * HH + 255) / 256, 256>>>();
    score_kernel<<<(ET * HH) / 8, 256>>>(att, Cout);
    alpha_kernel<<<(ET * HH + 255) / 256, 256>>>();
    init_out_kernel<<<(NN * Cout + 255) / 256, 256>>>(zout, gb, Cout);
    aggregate_kernel<<<ET, 256>>>(zout, Cout);
    if (act_after)
        lrelu_kernel<<<(NN * Cout + 255) / 256, 256>>>(zout, NN * Cout);
}

extern "C" void kernel_launch(void* const* d_in, const int* in_sizes, int n_in,
                              void* d_out, int out_size) {
    const float* x  = (const float*)d_in[0];
    const void*  ei = d_in[1];
    const float* w1l = (const float*)d_in[2];
    const float* b1l = (const float*)d_in[3];
    const float* w1r = (const float*)d_in[4];
    const float* b1r = (const float*)d_in[5];
    const float* att1 = (const float*)d_in[6];
    const float* gb1  = (const float*)d_in[7];
    const float* w2l = (const float*)d_in[8];
    const float* b2l = (const float*)d_in[9];
    const float* w2r = (const float*)d_in[10];
    const float* b2r = (const float*)d_in[11];
    const float* att2 = (const float*)d_in[12];
    const float* gb2  = (const float*)d_in[13];
    const float* w3l = (const float*)d_in[14];
    const float* b3l = (const float*)d_in[15];
    const float* w3r = (const float*)d_in[16];
    const float* b3r = (const float*)d_in[17];
    const float* att3 = (const float*)d_in[18];
    const float* gb3  = (const float*)d_in[19];
    const float* dw1 = (const float*)d_in[20];
    const float* db1 = (const float*)d_in[21];
    const float* dw2 = (const float*)d_in[22];
    const float* db2 = (const float*)d_in[23];
    const float* dw3 = (const float*)d_in[24];
    const float* db3 = (const float*)d_in[25];

    void* p;
    cudaGetSymbolAddress(&p, g_xl);   float* xl   = (float*)p;
    cudaGetSymbolAddress(&p, g_xr);   float* xr   = (float*)p;
    cudaGetSymbolAddress(&p, g_buf1); float* buf1 = (float*)p;
    cudaGetSymbolAddress(&p, g_buf2); float* buf2 = (float*)p;
    cudaGetSymbolAddress(&p, g_ah);   h_ah = (__nv_bfloat16*)p;
    cudaGetSymbolAddress(&p, g_al);   h_al = (__nv_bfloat16*)p;
    cudaGetSymbolAddress(&p, g_bh);   h_bh = (__nv_bfloat16*)p;
    cudaGetSymbolAddress(&p, g_bl);   h_bl = (__nv_bfloat16*)p;

    // edges (dtype-robust: int64 vs int32)
    detect_dtype_kernel<<<1, 256>>>(ei);
    build_edges_kernel<<<(ET + 255) / 256, 256>>>(ei);

    // ---- GAT layer 1 (Cin=4 -> fp32 GEMM path), Cout=128, HC=4096
    run_sgemm(x, w1l, b1l, xl, NN, HH * 128, 4, 0);
    run_sgemm(x, w1r, b1r, xr, NN, HH * 128, 4, 0);
    gat_attention(att1, gb1, buf1, 128, 1);

    // ---- GAT layer 2: Cin=128 (Kp=128), Cout=512, HC=16384
    convert_A(buf1, NN, 128, 128);
    run_tc_gemm(w2l, b2l, xl, NN, HH * 512, 128, 128, 0);
    run_tc_gemm(w2r, b2r, xr, NN, HH * 512, 128, 128, 0);
    gat_attention(att2, gb2, buf2, 512, 1);

    // ---- GAT layer 3: Cin=512 (Kp=512), Cout=1028, HC=32896
    convert_A(buf2, NN, 512, 512);
    run_tc_gemm(w3l, b3l, xl, NN, HH * 1028, 512, 512, 0);
    run_tc_gemm(w3r, b3r, xr, NN, HH * 1028, 512, 512, 0);
    gat_attention(att3, gb3, buf1, 1028, 0);

    // ---- decoder MLP
    convert_A(buf1, NN, 1028, 1056);
    run_tc_gemm(dw1, db1, buf2, NN, 512, 1028, 1056, 1);
    convert_A(buf2, NN, 512, 512);
    run_tc_gemm(dw2, db2, buf1, NN, 128, 512, 512, 1);
    run_sgemm(buf1, dw3, db3, (float*)d_out, NN, 2, 128, 0);

    (void)in_sizes; (void)n_in; (void)out_size;
}

// round 4
// speedup vs baseline: 2.5520x; 1.0145x over previous
#include <cuda_runtime.h>
#include <cuda_bf16.h>
#include <cstdint>

#define NN   1024      // nodes
#define EE   2048      // raw edges
#define ET   3072      // edges + self loops
#define HH   32        // heads
#define CMX  1028      // max per-head channel dim
#define KPMX 1088      // max padded K
#define BMAX 16842752  // 32896*512 max weight elements

// ---------------- scratch (device globals; no allocation allowed) ----------------
__device__ float         g_xl[(size_t)NN * HH * CMX];
__device__ float         g_xr[(size_t)NN * HH * CMX];
__device__ float         g_buf1[NN * CMX];
__device__ float         g_buf2[NN * CMX];
__device__ float         g_score[ET * HH];
__device__ float         g_alpha[ET * HH];
__device__ unsigned      g_smax[NN * HH];
__device__ float         g_denom[NN * HH];
__device__ int           g_src[ET];
__device__ int           g_dst[ET];
__device__ int           g_is64;
__device__ __nv_bfloat16 g_ah[NN * KPMX];
__device__ __nv_bfloat16 g_al[NN * KPMX];
__device__ __nv_bfloat16 g_bh0[BMAX];
__device__ __nv_bfloat16 g_bl0[BMAX];
__device__ __nv_bfloat16 g_bh1[BMAX];
__device__ __nv_bfloat16 g_bl1[BMAX];

// ---------------- helpers ----------------
__device__ __forceinline__ unsigned flipf(float f) {
    unsigned u = __float_as_uint(f);
    return u ^ ((unsigned)((int)u >> 31) | 0x80000000u);
}
__device__ __forceinline__ float unflipf(unsigned v) {
    unsigned m = (v & 0x80000000u) ? 0x80000000u : 0xFFFFFFFFu;
    return __uint_as_float(v ^ m);
}

// ---------------- edge dtype detection + edge build ----------------
__global__ void detect_dtype_kernel(const void* ei) {
    __shared__ int bad;
    if (threadIdx.x == 0) bad = 0;
    __syncthreads();
    const long long* p = (const long long*)ei;
    for (int i = threadIdx.x; i < EE; i += blockDim.x) {
        long long v = p[i];
        if (v < 0 || v >= NN) bad = 1;
    }
    __syncthreads();
    if (threadIdx.x == 0) g_is64 = !bad;
}

__global__ void build_edges_kernel(const void* ei) {
    int e = blockIdx.x * blockDim.x + threadIdx.x;
    if (e >= ET) return;
    if (e < EE) {
        if (g_is64) {
            const long long* p = (const long long*)ei;
            g_src[e] = (int)p[e];
            g_dst[e] = (int)p[EE + e];
        } else {
            const int* p = (const int*)ei;
            g_src[e] = p[e];
            g_dst[e] = p[EE + e];
        }
    } else {
        g_src[e] = e - EE;
        g_dst[e] = e - EE;
    }
}

// ---------------- fp32 -> bf16 hi/lo split with zero padding ----------------
__global__ void convert_pad_kernel(const float* __restrict__ src,
                                   __nv_bfloat16* __restrict__ hi,
                                   __nv_bfloat16* __restrict__ lo,
                                   int R, int Cc, int Rout, int Cout) {
    int i = blockIdx.x * blockDim.x + threadIdx.x;
    if (i >= Rout * Cout) return;
    int r = i / Cout, c = i - r * Cout;
    float v = (r < R && c < Cc) ? src[(size_t)r * Cc + c] : 0.f;
    __nv_bfloat16 h = __float2bfloat16(v);
    hi[i] = h;
    lo[i] = __float2bfloat16(v - __bfloat162float(h));
}

// ---------------- tensor-core GEMM (bf16x3 split, fp32 accum, cp.async pipeline) ----------------
// C[M,Nn] = A[M,Kp] @ B[Kp,Nn] + bias, optional leakyrelu(0.01).
// M%128==0, Nn%128==0, Kp%32==0. BM=BN=128, BK=32, 256 threads.
// blockIdx.z selects the (B, bias, C) tuple -> fuses lin_l / lin_r.
#define ASTR 40    // bf16 row stride for A tiles [128][32] (80B rows, 16B-aligned)
#define BSTR 136   // bf16 row stride for B tiles [32][128] (272B rows)
#define AHOFF 0
#define ALOFF 10240
#define BHOFF 20480
#define BLOFF 29184
#define BUFSZ 37888
#define DSMEM (2 * BUFSZ)

#define LDMX4(R0,R1,R2,R3,ADDR) \
    asm volatile("ldmatrix.sync.aligned.m8n8.x4.shared.b16 {%0,%1,%2,%3}, [%4];" \
        : "=r"(R0), "=r"(R1), "=r"(R2), "=r"(R3) : "r"(ADDR))
#define LDMX2T(R0,R1,ADDR) \
    asm volatile("ldmatrix.sync.aligned.m8n8.x2.trans.shared.b16 {%0,%1}, [%2];" \
        : "=r"(R0), "=r"(R1) : "r"(ADDR))
#define MMA16816(C0,C1,C2,C3,A0,A1,A2,A3,B0,B1) \
    asm volatile("mma.sync.aligned.m16n8k16.row.col.f32.bf16.bf16.f32 " \
        "{%0,%1,%2,%3}, {%4,%5,%6,%7}, {%8,%9}, {%0,%1,%2,%3};" \
        : "+f"(C0), "+f"(C1), "+f"(C2), "+f"(C3) \
        : "r"(A0), "r"(A1), "r"(A2), "r"(A3), "r"(B0), "r"(B1))
#define CP16(SADDR, GPTR) \
    asm volatile("cp.async.ca.shared.global [%0], [%1], 16;" :: "r"(SADDR), "l"(GPTR))

__global__ __launch_bounds__(256) void tc_gemm_kernel(
    const __nv_bfloat16* __restrict__ Ah, const __nv_bfloat16* __restrict__ Al,
    const __nv_bfloat16* __restrict__ Bh0, const __nv_bfloat16* __restrict__ Bl0,
    const __nv_bfloat16* __restrict__ Bh1, const __nv_bfloat16* __restrict__ Bl1,
    const float* __restrict__ bias0, const float* __restrict__ bias1,
    float* __restrict__ C0, float* __restrict__ C1,
    int Nn, int Kp, int act)
{
    extern __shared__ char smem[];
    const uint32_t sbase = (uint32_t)__cvta_generic_to_shared(smem);

    const int tid  = threadIdx.x;
    const int warp = tid >> 5;
    const int lane = tid & 31;
    const int wm = (warp >> 2) * 64;
    const int wn = (warp & 3) * 32;
    const int bx = blockIdx.x * 128;
    const int by = blockIdx.y * 128;
    const int z  = blockIdx.z;

    const __nv_bfloat16* Bh = z ? Bh1 : Bh0;
    const __nv_bfloat16* Bl = z ? Bl1 : Bl0;
    const float* bias = z ? bias1 : bias0;
    float* C = z ? C1 : C0;

    float acc[4][4][4];
#pragma unroll
    for (int mi = 0; mi < 4; mi++)
#pragma unroll
        for (int ni = 0; ni < 4; ni++)
#pragma unroll
            for (int k = 0; k < 4; k++) acc[mi][ni][k] = 0.f;

    const int nc = Kp >> 5;

    // async tile load: A 128x32 (hi+lo), B 32x128 (hi+lo)
    auto load_tile = [&](int c, int b) {
        const int k0 = c << 5;
        const uint32_t base = sbase + b * BUFSZ;
#pragma unroll
        for (int j = 0; j < 2; j++) {
            int idx = tid + j * 256;
            int row = idx >> 2, seg = idx & 3;
            size_t go = (size_t)(by + row) * Kp + k0 + seg * 8;
            uint32_t so = base + (uint32_t)(row * ASTR + seg * 8) * 2;
            CP16(so + AHOFF, Ah + go);
            CP16(so + ALOFF, Al + go);
        }
#pragma unroll
        for (int j = 0; j < 2; j++) {
            int idx = tid + j * 256;
            int row = idx >> 4, seg = idx & 15;
            size_t go = (size_t)(k0 + row) * Nn + bx + seg * 8;
            uint32_t so = base + (uint32_t)(row * BSTR + seg * 8) * 2;
            CP16(so + BHOFF, Bh + go);
            CP16(so + BLOFF, Bl + go);
        }
        asm volatile("cp.async.commit_group;" ::: "memory");
    };

    const int r8 = lane & 7;
    const int gA = lane >> 3;
    const int gB = (lane >> 3) & 1;

    load_tile(0, 0);

    for (int c = 0; c < nc; c++) {
        const int b = c & 1;
        if (c + 1 < nc) {
            load_tile(c + 1, (c + 1) & 1);
            asm volatile("cp.async.wait_group 1;" ::: "memory");
        } else {
            asm volatile("cp.async.wait_group 0;" ::: "memory");
        }
        __syncthreads();

        const uint32_t base = sbase + b * BUFSZ;
#pragma unroll
        for (int ks = 0; ks < 2; ks++) {
            const int ko = ks * 16;
            uint32_t ah[4][4], al[4][4], bh[4][2], bl[4][2];
#pragma unroll
            for (int mi = 0; mi < 4; mi++) {
                int row = wm + mi * 16 + r8 + (gA & 1) * 8;
                int col = ko + (gA >> 1) * 8;
                uint32_t off = (uint32_t)(row * ASTR + col) * 2;
                LDMX4(ah[mi][0], ah[mi][1], ah[mi][2], ah[mi][3], base + AHOFF + off);
                LDMX4(al[mi][0], al[mi][1], al[mi][2], al[mi][3], base + ALOFF + off);
            }
#pragma unroll
            for (int ni = 0; ni < 4; ni++) {
                int row = ko + gB * 8 + r8;
                int col = wn + ni * 8;
                uint32_t off = (uint32_t)(row * BSTR + col) * 2;
                LDMX2T(bh[ni][0], bh[ni][1], base + BHOFF + off);
                LDMX2T(bl[ni][0], bl[ni][1], base + BLOFF + off);
            }
#pragma unroll
            for (int mi = 0; mi < 4; mi++) {
#pragma unroll
                for (int ni = 0; ni < 4; ni++) {
                    float* cc = acc[mi][ni];
                    MMA16816(cc[0], cc[1], cc[2], cc[3],
                             ah[mi][0], ah[mi][1], ah[mi][2], ah[mi][3],
                             bh[ni][0], bh[ni][1]);
                    MMA16816(cc[0], cc[1], cc[2], cc[3],
                             ah[mi][0], ah[mi][1], ah[mi][2], ah[mi][3],
                             bl[ni][0], bl[ni][1]);
                    MMA16816(cc[0], cc[1], cc[2], cc[3],
                             al[mi][0], al[mi][1], al[mi][2], al[mi][3],
                             bh[ni][0], bh[ni][1]);
                }
            }
        }
        __syncthreads();
    }

    // epilogue
    const int g = lane >> 2, tig = lane & 3;
#pragma unroll
    for (int mi = 0; mi < 4; mi++) {
#pragma unroll
        for (int ni = 0; ni < 4; ni++) {
            int row = by + wm + mi * 16 + g;
            int col = bx + wn + ni * 8 + tig * 2;
            float bv0 = bias[col], bv1 = bias[col + 1];
            float v0 = acc[mi][ni][0] + bv0;
            float v1 = acc[mi][ni][1] + bv1;
            float v2 = acc[mi][ni][2] + bv0;
            float v3 = acc[mi][ni][3] + bv1;
            if (act) {
                v0 = (v0 > 0.f) ? v0 : 0.01f * v0;
                v1 = (v1 > 0.f) ? v1 : 0.01f * v1;
                v2 = (v2 > 0.f) ? v2 : 0.01f * v2;
                v3 = (v3 > 0.f) ? v3 : 0.01f * v3;
            }
            C[(size_t)row * Nn + col]           = v0;
            C[(size_t)row * Nn + col + 1]       = v1;
            C[(size_t)(row + 8) * Nn + col]     = v2;
            C[(size_t)(row + 8) * Nn + col + 1] = v3;
        }
    }
}

// ---------------- fp32 SGEMM (small shapes: K=4 layer-1, final N=2) ----------------
__global__ void sgemm_kernel(const float* __restrict__ A, const float* __restrict__ B,
                             const float* __restrict__ bias, float* __restrict__ C,
                             int M, int Nn, int K, int act) {
    __shared__ float As[8][128];
    __shared__ float Bs[8][128];
    const int bx = blockIdx.x * 128;
    const int by = blockIdx.y * 128;
    const int tid = threadIdx.x;
    const int tr = tid / 16;
    const int tc = tid % 16;

    float acc[8][8];
#pragma unroll
    for (int i = 0; i < 8; i++)
#pragma unroll
        for (int j = 0; j < 8; j++) acc[i][j] = 0.f;

    const int row_a = tid / 2;
    const int cola0 = (tid % 2) * 4;
    const int row_b = tid / 32;
    const int colb0 = (tid % 32) * 4;

    for (int k0 = 0; k0 < K; k0 += 8) {
#pragma unroll
        for (int i = 0; i < 4; i++) {
            int r = by + row_a;
            int kk = k0 + cola0 + i;
            As[cola0 + i][row_a] = (r < M && kk < K) ? A[(size_t)r * K + kk] : 0.f;
        }
#pragma unroll
        for (int i = 0; i < 4; i++) {
            int kk = k0 + row_b;
            int c = bx + colb0 + i;
            Bs[row_b][colb0 + i] = (kk < K && c < Nn) ? B[(size_t)kk * Nn + c] : 0.f;
        }
        __syncthreads();
#pragma unroll
        for (int kk = 0; kk < 8; kk++) {
            float a[8], b[8];
#pragma unroll
            for (int i = 0; i < 8; i++) a[i] = As[kk][tr + 16 * i];
#pragma unroll
            for (int j = 0; j < 8; j++) b[j] = Bs[kk][tc + 16 * j];
#pragma unroll
            for (int i = 0; i < 8; i++)
#pragma unroll
                for (int j = 0; j < 8; j++) acc[i][j] += a[i] * b[j];
        }
        __syncthreads();
    }

#pragma unroll
    for (int i = 0; i < 8; i++) {
        int r = by + tr + 16 * i;
        if (r >= M) continue;
#pragma unroll
        for (int j = 0; j < 8; j++) {
            int c = bx + tc + 16 * j;
            if (c >= Nn) continue;
            float v = acc[i][j] + bias[c];
            if (act) v = (v > 0.f) ? v : 0.01f * v;
            C[(size_t)r * Nn + c] = v;
        }
    }
}

// ---------------- softmax state init ----------------
__global__ void init_soft_kernel() {
    int i = blockIdx.x * blockDim.x + threadIdx.x;
    if (i < NN * HH) {
        g_smax[i] = 0u;
        g_denom[i] = 0.f;
    }
}

// ---------------- per-(edge,head) attention score (float4) ----------------
__global__ void score_kernel(const float* __restrict__ att, int C) {
    int gw = (blockIdx.x * blockDim.x + threadIdx.x) >> 5;
    int lane = threadIdx.x & 31;
    if (gw >= ET * HH) return;
    int e = gw / HH, h = gw % HH;
    int s = g_src[e], d = g_dst[e];
    const int n4 = C >> 2;
    const float4* xl = (const float4*)(g_xl + ((size_t)s * HH + h) * C);
    const float4* xr = (const float4*)(g_xr + ((size_t)d * HH + h) * C);
    const float4* at = (const float4*)(att + h * C);
    float acc = 0.f;
    for (int c = lane; c < n4; c += 32) {
        float4 a = xl[c], b = xr[c], w = at[c];
        float v0 = a.x + b.x, v1 = a.y + b.y, v2 = a.z + b.z, v3 = a.w + b.w;
        v0 = (v0 > 0.f) ? v0 : 0.2f * v0;
        v1 = (v1 > 0.f) ? v1 : 0.2f * v1;
        v2 = (v2 > 0.f) ? v2 : 0.2f * v2;
        v3 = (v3 > 0.f) ? v3 : 0.2f * v3;
        acc += w.x * v0 + w.y * v1 + w.z * v2 + w.w * v3;
    }
#pragma unroll
    for (int o = 16; o; o >>= 1) acc += __shfl_xor_sync(0xffffffffu, acc, o);
    if (lane == 0) {
        g_score[e * HH + h] = acc;
        atomicMax(&g_smax[d * HH + h], flipf(acc));
    }
}

// ---------------- alpha = exp(score - max); accumulate denominators ----------------
__global__ void alpha_kernel() {
    int i = blockIdx.x * blockDim.x + threadIdx.x;
    if (i >= ET * HH) return;
    int e = i / HH, h = i % HH;
    int d = g_dst[e];
    float m = unflipf(g_smax[d * HH + h]);
    float a = expf(g_score[i] - m);
    g_alpha[i] = a;
    atomicAdd(&g_denom[d * HH + h], a);
}

// ---------------- out init with bias ----------------
__global__ void init_out_kernel(float* __restrict__ out, const float* __restrict__ bias, int C) {
    int i = blockIdx.x * blockDim.x + threadIdx.x;
    if (i < NN * C) out[i] = bias[i % C];
}

// ---------------- aggregation: one block per edge (float4) ----------------
__global__ void aggregate_kernel(float* __restrict__ out, int C) {
    int e = blockIdx.x;
    __shared__ float a[HH];
    int d = g_dst[e], s = g_src[e];
    if (threadIdx.x < HH) {
        int h = threadIdx.x;
        a[h] = g_alpha[e * HH + h] / g_denom[d * HH + h] * (1.0f / HH);
    }
    __syncthreads();
    const int n4 = C >> 2;
    const float4* xl = (const float4*)(g_xl + (size_t)s * HH * C);
    float* o = out + (size_t)d * C;
    for (int c4 = threadIdx.x; c4 < n4; c4 += blockDim.x) {
        float4 acc = make_float4(0.f, 0.f, 0.f, 0.f);
#pragma unroll 8
        for (int h = 0; h < HH; h++) {
            float4 v = xl[(size_t)h * n4 + c4];
            float w = a[h];
            acc.x += w * v.x; acc.y += w * v.y;
            acc.z += w * v.z; acc.w += w * v.w;
        }
        atomicAdd(&o[c4 * 4 + 0], acc.x);
        atomicAdd(&o[c4 * 4 + 1], acc.y);
        atomicAdd(&o[c4 * 4 + 2], acc.z);
        atomicAdd(&o[c4 * 4 + 3], acc.w);
    }
}

// ---------------- elementwise leaky relu (0.01) ----------------
__global__ void lrelu_kernel(float* __restrict__ z, int n) {
    int i = blockIdx.x * blockDim.x + threadIdx.x;
    if (i < n) {
        float v = z[i];
        z[i] = (v > 0.f) ? v : 0.01f * v;
    }
}

// ---------------- host-side orchestration ----------------
static __nv_bfloat16 *h_ah, *h_al, *h_bh0, *h_bl0, *h_bh1, *h_bl1;

static void run_sgemm(const float* A, const float* B, const float* bias, float* C,
                      int M, int Nn, int K, int act) {
    dim3 grid((Nn + 127) / 128, (M + 127) / 128);
    sgemm_kernel<<<grid, 256>>>(A, B, bias, C, M, Nn, K, act);
}

static void convert_A(const float* A, int M, int K, int Kp) {
    int n = M * Kp;
    convert_pad_kernel<<<(n + 255) / 256, 256>>>(A, h_ah, h_al, M, K, M, Kp);
}

// fused pair GEMM (z=2) or single (z=1)
static void run_tc_pair(const float* B0, const float* bias0, float* C0,
                        const float* B1, const float* bias1, float* C1,
                        int M, int Nn, int K, int Kp, int act, int nz) {
    int n = Kp * Nn;
    convert_pad_kernel<<<(n + 255) / 256, 256>>>(B0, h_bh0, h_bl0, K, Nn, Kp, Nn);
    if (nz == 2)
        convert_pad_kernel<<<(n + 255) / 256, 256>>>(B1, h_bh1, h_bl1, K, Nn, Kp, Nn);
    cudaFuncSetAttribute(tc_gemm_kernel, cudaFuncAttributeMaxDynamicSharedMemorySize, DSMEM);
    dim3 grid(Nn / 128, M / 128, nz);
    tc_gemm_kernel<<<grid, 256, DSMEM>>>(h_ah, h_al, h_bh0, h_bl0, h_bh1, h_bl1,
                                         bias0, bias1, C0, C1, Nn, Kp, act);
}

static void gat_attention(const float* att, const float* gb, float* zout,
                          int Cout, int act_after) {
    init_soft_kernel<<<(NN * HH + 255) / 256, 256>>>();
    score_kernel<<<(ET * HH) / 8, 256>>>(att, Cout);
    alpha_kernel<<<(ET * HH + 255) / 256, 256>>>();
    init_out_kernel<<<(NN * Cout + 255) / 256, 256>>>(zout, gb, Cout);
    aggregate_kernel<<<ET, 256>>>(zout, Cout);
    if (act_after)
        lrelu_kernel<<<(NN * Cout + 255) / 256, 256>>>(zout, NN * Cout);
}

extern "C" void kernel_launch(void* const* d_in, const int* in_sizes, int n_in,
                              void* d_out, int out_size) {
    const float* x  = (const float*)d_in[0];
    const void*  ei = d_in[1];
    const float* w1l = (const float*)d_in[2];
    const float* b1l = (const float*)d_in[3];
    const float* w1r = (const float*)d_in[4];
    const float* b1r = (const float*)d_in[5];
    const float* att1 = (const float*)d_in[6];
    const float* gb1  = (const float*)d_in[7];
    const float* w2l = (const float*)d_in[8];
    const float* b2l = (const float*)d_in[9];
    const float* w2r = (const float*)d_in[10];
    const float* b2r = (const float*)d_in[11];
    const float* att2 = (const float*)d_in[12];
    const float* gb2  = (const float*)d_in[13];
    const float* w3l = (const float*)d_in[14];
    const float* b3l = (const float*)d_in[15];
    const float* w3r = (const float*)d_in[16];
    const float* b3r = (const float*)d_in[17];
    const float* att3 = (const float*)d_in[18];
    const float* gb3  = (const float*)d_in[19];
    const float* dw1 = (const float*)d_in[20];
    const float* db1 = (const float*)d_in[21];
    const float* dw2 = (const float*)d_in[22];
    const float* db2 = (const float*)d_in[23];
    const float* dw3 = (const float*)d_in[24];
    const float* db3 = (const float*)d_in[25];

    void* p;
    cudaGetSymbolAddress(&p, g_xl);   float* xl   = (float*)p;
    cudaGetSymbolAddress(&p, g_xr);   float* xr   = (float*)p;
    cudaGetSymbolAddress(&p, g_buf1); float* buf1 = (float*)p;
    cudaGetSymbolAddress(&p, g_buf2); float* buf2 = (float*)p;
    cudaGetSymbolAddress(&p, g_ah);   h_ah  = (__nv_bfloat16*)p;
    cudaGetSymbolAddress(&p, g_al);   h_al  = (__nv_bfloat16*)p;
    cudaGetSymbolAddress(&p, g_bh0);  h_bh0 = (__nv_bfloat16*)p;
    cudaGetSymbolAddress(&p, g_bl0);  h_bl0 = (__nv_bfloat16*)p;
    cudaGetSymbolAddress(&p, g_bh1);  h_bh1 = (__nv_bfloat16*)p;
    cudaGetSymbolAddress(&p, g_bl1);  h_bl1 = (__nv_bfloat16*)p;

    // edges (dtype-robust: int64 vs int32)
    detect_dtype_kernel<<<1, 256>>>(ei);
    build_edges_kernel<<<(ET + 255) / 256, 256>>>(ei);

    // ---- GAT layer 1 (Cin=4 -> fp32 GEMM path), Cout=128, HC=4096
    run_sgemm(x, w1l, b1l, xl, NN, HH * 128, 4, 0);
    run_sgemm(x, w1r, b1r, xr, NN, HH * 128, 4, 0);
    gat_attention(att1, gb1, buf1, 128, 1);

    // ---- GAT layer 2: Cin=128 (Kp=128), Cout=512, HC=16384
    convert_A(buf1, NN, 128, 128);
    run_tc_pair(w2l, b2l, xl, w2r, b2r, xr, NN, HH * 512, 128, 128, 0, 2);
    gat_attention(att2, gb2, buf2, 512, 1);

    // ---- GAT layer 3: Cin=512 (Kp=512), Cout=1028, HC=32896
    convert_A(buf2, NN, 512, 512);
    run_tc_pair(w3l, b3l, xl, w3r, b3r, xr, NN, HH * 1028, 512, 512, 0, 2);
    gat_attention(att3, gb3, buf1, 1028, 0);

    // ---- decoder MLP
    convert_A(buf1, NN, 1028, 1088);
    run_tc_pair(dw1, db1, buf2, 0, 0, 0, NN, 512, 1028, 1088, 1, 1);
    convert_A(buf2, NN, 512, 512);
    run_tc_pair(dw2, db2, buf1, 0, 0, 0, NN, 128, 512, 512, 1, 1);
    run_sgemm(buf1, dw3, db3, (float*)d_out, NN, 2, 128, 0);

    (void)in_sizes; (void)n_in; (void)out_size;
}

// round 5
// speedup vs baseline: 2.6391x; 1.0341x over previous
#include <cuda_runtime.h>
#include <cuda_bf16.h>
#include <cstdint>

#define NN   1024      // nodes
#define EE   2048      // raw edges
#define ET   3072      // edges + self loops
#define HH   32        // heads
#define CMX  1028      // max per-head channel dim
#define KPMX 1088      // max padded K
#define BMAX 16842752  // 32896*512 max weight elements

// ---------------- scratch (device globals; no allocation allowed) ----------------
__device__ float         g_xl[(size_t)NN * HH * CMX];
__device__ float         g_xr[(size_t)NN * HH * CMX];
__device__ float         g_buf1[NN * CMX];
__device__ float         g_buf2[NN * CMX];
__device__ float         g_score[ET * HH];
__device__ float         g_alpha[ET * HH];
__device__ unsigned      g_smax[3 * NN * HH];
__device__ float         g_denom[3 * NN * HH];
__device__ int           g_src[ET];
__device__ int           g_dst[ET];
__device__ int           g_rank[ET];
__device__ int           g_deg[NN];
__device__ int           g_rowptr[NN + 1];
__device__ int           g_eid[ET];
__device__ int           g_is64;
__device__ __nv_bfloat16 g_ah[NN * KPMX];
__device__ __nv_bfloat16 g_al[NN * KPMX];
__device__ __nv_bfloat16 g_bh0[BMAX];
__device__ __nv_bfloat16 g_bl0[BMAX];
__device__ __nv_bfloat16 g_bh1[BMAX];
__device__ __nv_bfloat16 g_bl1[BMAX];

// ---------------- helpers ----------------
__device__ __forceinline__ unsigned flipf(float f) {
    unsigned u = __float_as_uint(f);
    return u ^ ((unsigned)((int)u >> 31) | 0x80000000u);
}
__device__ __forceinline__ float unflipf(unsigned v) {
    unsigned m = (v & 0x80000000u) ? 0x80000000u : 0xFFFFFFFFu;
    return __uint_as_float(v ^ m);
}

// ---------------- edge dtype detection ----------------
__global__ void detect_dtype_kernel(const void* ei) {
    __shared__ int bad;
    if (threadIdx.x == 0) bad = 0;
    __syncthreads();
    const long long* p = (const long long*)ei;
    for (int i = threadIdx.x; i < EE; i += blockDim.x) {
        long long v = p[i];
        if (v < 0 || v >= NN) bad = 1;
    }
    __syncthreads();
    if (threadIdx.x == 0) g_is64 = !bad;
}

// ---------------- edge build + softmax-state init (all 3 layers) + deg zero ----------------
__global__ void build_edges_kernel(const void* ei) {
    int i = blockIdx.x * blockDim.x + threadIdx.x;
    if (i < ET) {
        if (i < EE) {
            if (g_is64) {
                const long long* p = (const long long*)ei;
                g_src[i] = (int)p[i];
                g_dst[i] = (int)p[EE + i];
            } else {
                const int* p = (const int*)ei;
                g_src[i] = p[i];
                g_dst[i] = p[EE + i];
            }
        } else {
            g_src[i] = i - EE;
            g_dst[i] = i - EE;
        }
    }
    if (i < 3 * NN * HH) {
        g_smax[i] = 0u;
        g_denom[i] = 0.f;
    }
    if (i < NN) g_deg[i] = 0;
}

// ---------------- CSR build (deterministic) ----------------
__global__ void csr_rank_kernel() {
    __shared__ int sd[ET];
    int tid = threadIdx.x;
    for (int i = tid; i < ET; i += blockDim.x) sd[i] = g_dst[i];
    __syncthreads();
    int e = blockIdx.x * blockDim.x + tid;
    if (e < ET) {
        int d = sd[e], r = 0;
        for (int e2 = 0; e2 < e; e2++) r += (sd[e2] == d);
        g_rank[e] = r;
        atomicAdd(&g_deg[d], 1);
    }
}

__global__ void csr_scan_kernel() {
    __shared__ int s[NN];
    int t = threadIdx.x;
    s[t] = g_deg[t];
    __syncthreads();
    for (int o = 1; o < NN; o <<= 1) {
        int v = (t >= o) ? s[t - o] : 0;
        __syncthreads();
        s[t] += v;
        __syncthreads();
    }
    g_rowptr[t + 1] = s[t];
    if (t == 0) g_rowptr[0] = 0;
}

__global__ void csr_place_kernel() {
    int e = blockIdx.x * blockDim.x + threadIdx.x;
    if (e < ET) g_eid[g_rowptr[g_dst[e]] + g_rank[e]] = e;
}

// ---------------- fp32 -> bf16 hi/lo split (A: col pad, float4) ----------------
__global__ void convertA_kernel(const float* __restrict__ src,
                                int M, int K, int Kp) {
    int i4 = blockIdx.x * blockDim.x + threadIdx.x;
    int tot = (M * Kp) >> 2;
    if (i4 >= tot) return;
    int kp4 = Kp >> 2;
    int r = i4 / kp4, c4 = (i4 - r * kp4) << 2;
    float v[4];
    if (c4 + 3 < K) {
        float4 f = *(const float4*)(src + (size_t)r * K + c4);
        v[0] = f.x; v[1] = f.y; v[2] = f.z; v[3] = f.w;
    } else {
#pragma unroll
        for (int j = 0; j < 4; j++)
            v[j] = (c4 + j < K) ? src[(size_t)r * K + c4 + j] : 0.f;
    }
    __nv_bfloat162 h2[2], l2[2];
#pragma unroll
    for (int j = 0; j < 2; j++) {
        __nv_bfloat16 h0 = __float2bfloat16(v[2 * j]);
        __nv_bfloat16 h1 = __float2bfloat16(v[2 * j + 1]);
        h2[j] = __nv_bfloat162(h0, h1);
        l2[j] = __nv_bfloat162(__float2bfloat16(v[2 * j] - __bfloat162float(h0)),
                               __float2bfloat16(v[2 * j + 1] - __bfloat162float(h1)));
    }
    size_t o = (size_t)r * Kp + c4;
    *(__nv_bfloat162*)(g_ah + o)     = h2[0];
    *(__nv_bfloat162*)(g_ah + o + 2) = h2[1];
    *(__nv_bfloat162*)(g_al + o)     = l2[0];
    *(__nv_bfloat162*)(g_al + o + 2) = l2[1];
}

// ---------------- fp32 [K,Nn] -> bf16 hi/lo, row pad to Kp; pair fused via z ----------------
__global__ void convertB_kernel(const float* __restrict__ B0,
                                const float* __restrict__ B1,
                                int K, int Nn, int Kp) {
    int i4 = blockIdx.x * blockDim.x + threadIdx.x;
    int tot = (Kp * Nn) >> 2;
    if (i4 >= tot) return;
    const float* src = blockIdx.y ? B1 : B0;
    __nv_bfloat16* hi = blockIdx.y ? g_bh1 : g_bh0;
    __nv_bfloat16* lo = blockIdx.y ? g_bl1 : g_bl0;
    int n4 = Nn >> 2;
    int r = i4 / n4, c4 = (i4 - r * n4) << 2;
    float v[4];
    if (r < K) {
        float4 f = *(const float4*)(src + (size_t)r * Nn + c4);
        v[0] = f.x; v[1] = f.y; v[2] = f.z; v[3] = f.w;
    } else {
        v[0] = v[1] = v[2] = v[3] = 0.f;
    }
    __nv_bfloat162 h2[2], l2[2];
#pragma unroll
    for (int j = 0; j < 2; j++) {
        __nv_bfloat16 h0 = __float2bfloat16(v[2 * j]);
        __nv_bfloat16 h1 = __float2bfloat16(v[2 * j + 1]);
        h2[j] = __nv_bfloat162(h0, h1);
        l2[j] = __nv_bfloat162(__float2bfloat16(v[2 * j] - __bfloat162float(h0)),
                               __float2bfloat16(v[2 * j + 1] - __bfloat162float(h1)));
    }
    size_t o = (size_t)r * Nn + c4;
    *(__nv_bfloat162*)(hi + o)     = h2[0];
    *(__nv_bfloat162*)(hi + o + 2) = h2[1];
    *(__nv_bfloat162*)(lo + o)     = l2[0];
    *(__nv_bfloat162*)(lo + o + 2) = l2[1];
}

// ---------------- tensor-core GEMM (bf16x3 split, fp32 accum, cp.async pipeline) ----------------
#define ASTR 40
#define BSTR 136
#define AHOFF 0
#define ALOFF 10240
#define BHOFF 20480
#define BLOFF 29184
#define BUFSZ 37888
#define DSMEM (2 * BUFSZ)

#define LDMX4(R0,R1,R2,R3,ADDR) \
    asm volatile("ldmatrix.sync.aligned.m8n8.x4.shared.b16 {%0,%1,%2,%3}, [%4];" \
        : "=r"(R0), "=r"(R1), "=r"(R2), "=r"(R3) : "r"(ADDR))
#define LDMX2T(R0,R1,ADDR) \
    asm volatile("ldmatrix.sync.aligned.m8n8.x2.trans.shared.b16 {%0,%1}, [%2];" \
        : "=r"(R0), "=r"(R1) : "r"(ADDR))
#define MMA16816(C0,C1,C2,C3,A0,A1,A2,A3,B0,B1) \
    asm volatile("mma.sync.aligned.m16n8k16.row.col.f32.bf16.bf16.f32 " \
        "{%0,%1,%2,%3}, {%4,%5,%6,%7}, {%8,%9}, {%0,%1,%2,%3};" \
        : "+f"(C0), "+f"(C1), "+f"(C2), "+f"(C3) \
        : "r"(A0), "r"(A1), "r"(A2), "r"(A3), "r"(B0), "r"(B1))
#define CP16(SADDR, GPTR) \
    asm volatile("cp.async.ca.shared.global [%0], [%1], 16;" :: "r"(SADDR), "l"(GPTR))

__global__ __launch_bounds__(256) void tc_gemm_kernel(
    const __nv_bfloat16* __restrict__ Ah, const __nv_bfloat16* __restrict__ Al,
    const __nv_bfloat16* __restrict__ Bh0, const __nv_bfloat16* __restrict__ Bl0,
    const __nv_bfloat16* __restrict__ Bh1, const __nv_bfloat16* __restrict__ Bl1,
    const float* __restrict__ bias0, const float* __restrict__ bias1,
    float* __restrict__ C0, float* __restrict__ C1,
    int Nn, int Kp, int act)
{
    extern __shared__ char smem[];
    const uint32_t sbase = (uint32_t)__cvta_generic_to_shared(smem);

    const int tid  = threadIdx.x;
    const int warp = tid >> 5;
    const int lane = tid & 31;
    const int wm = (warp >> 2) * 64;
    const int wn = (warp & 3) * 32;
    const int bx = blockIdx.x * 128;
    const int by = blockIdx.y * 128;
    const int z  = blockIdx.z;

    const __nv_bfloat16* Bh = z ? Bh1 : Bh0;
    const __nv_bfloat16* Bl = z ? Bl1 : Bl0;
    const float* bias = z ? bias1 : bias0;
    float* C = z ? C1 : C0;

    float acc[4][4][4];
#pragma unroll
    for (int mi = 0; mi < 4; mi++)
#pragma unroll
        for (int ni = 0; ni < 4; ni++)
#pragma unroll
            for (int k = 0; k < 4; k++) acc[mi][ni][k] = 0.f;

    const int nc = Kp >> 5;

    auto load_tile = [&](int c, int b) {
        const int k0 = c << 5;
        const uint32_t base = sbase + b * BUFSZ;
#pragma unroll
        for (int j = 0; j < 2; j++) {
            int idx = tid + j * 256;
            int row = idx >> 2, seg = idx & 3;
            size_t go = (size_t)(by + row) * Kp + k0 + seg * 8;
            uint32_t so = base + (uint32_t)(row * ASTR + seg * 8) * 2;
            CP16(so + AHOFF, Ah + go);
            CP16(so + ALOFF, Al + go);
        }
#pragma unroll
        for (int j = 0; j < 2; j++) {
            int idx = tid + j * 256;
            int row = idx >> 4, seg = idx & 15;
            size_t go = (size_t)(k0 + row) * Nn + bx + seg * 8;
            uint32_t so = base + (uint32_t)(row * BSTR + seg * 8) * 2;
            CP16(so + BHOFF, Bh + go);
            CP16(so + BLOFF, Bl + go);
        }
        asm volatile("cp.async.commit_group;" ::: "memory");
    };

    const int r8 = lane & 7;
    const int gA = lane >> 3;
    const int gB = (lane >> 3) & 1;

    load_tile(0, 0);

    for (int c = 0; c < nc; c++) {
        const int b = c & 1;
        if (c + 1 < nc) {
            load_tile(c + 1, (c + 1) & 1);
            asm volatile("cp.async.wait_group 1;" ::: "memory");
        } else {
            asm volatile("cp.async.wait_group 0;" ::: "memory");
        }
        __syncthreads();

        const uint32_t base = sbase + b * BUFSZ;
#pragma unroll
        for (int ks = 0; ks < 2; ks++) {
            const int ko = ks * 16;
            uint32_t ah[4][4], al[4][4], bh[4][2], bl[4][2];
#pragma unroll
            for (int mi = 0; mi < 4; mi++) {
                int row = wm + mi * 16 + r8 + (gA & 1) * 8;
                int col = ko + (gA >> 1) * 8;
                uint32_t off = (uint32_t)(row * ASTR + col) * 2;
                LDMX4(ah[mi][0], ah[mi][1], ah[mi][2], ah[mi][3], base + AHOFF + off);
                LDMX4(al[mi][0], al[mi][1], al[mi][2], al[mi][3], base + ALOFF + off);
            }
#pragma unroll
            for (int ni = 0; ni < 4; ni++) {
                int row = ko + gB * 8 + r8;
                int col = wn + ni * 8;
                uint32_t off = (uint32_t)(row * BSTR + col) * 2;
                LDMX2T(bh[ni][0], bh[ni][1], base + BHOFF + off);
                LDMX2T(bl[ni][0], bl[ni][1], base + BLOFF + off);
            }
#pragma unroll
            for (int mi = 0; mi < 4; mi++) {
#pragma unroll
                for (int ni = 0; ni < 4; ni++) {
                    float* cc = acc[mi][ni];
                    MMA16816(cc[0], cc[1], cc[2], cc[3],
                             ah[mi][0], ah[mi][1], ah[mi][2], ah[mi][3],
                             bh[ni][0], bh[ni][1]);
                    MMA16816(cc[0], cc[1], cc[2], cc[3],
                             ah[mi][0], ah[mi][1], ah[mi][2], ah[mi][3],
                             bl[ni][0], bl[ni][1]);
                    MMA16816(cc[0], cc[1], cc[2], cc[3],
                             al[mi][0], al[mi][1], al[mi][2], al[mi][3],
                             bh[ni][0], bh[ni][1]);
                }
            }
        }
        __syncthreads();
    }

    const int g = lane >> 2, tig = lane & 3;
#pragma unroll
    for (int mi = 0; mi < 4; mi++) {
#pragma unroll
        for (int ni = 0; ni < 4; ni++) {
            int row = by + wm + mi * 16 + g;
            int col = bx + wn + ni * 8 + tig * 2;
            float bv0 = bias[col], bv1 = bias[col + 1];
            float v0 = acc[mi][ni][0] + bv0;
            float v1 = acc[mi][ni][1] + bv1;
            float v2 = acc[mi][ni][2] + bv0;
            float v3 = acc[mi][ni][3] + bv1;
            if (act) {
                v0 = (v0 > 0.f) ? v0 : 0.01f * v0;
                v1 = (v1 > 0.f) ? v1 : 0.01f * v1;
                v2 = (v2 > 0.f) ? v2 : 0.01f * v2;
                v3 = (v3 > 0.f) ? v3 : 0.01f * v3;
            }
            C[(size_t)row * Nn + col]           = v0;
            C[(size_t)row * Nn + col + 1]       = v1;
            C[(size_t)(row + 8) * Nn + col]     = v2;
            C[(size_t)(row + 8) * Nn + col + 1] = v3;
        }
    }
}

// ---------------- fp32 SGEMM with z-pair fusion (K=4 layer-1; final N=2) ----------------
__global__ void sgemm_kernel(const float* __restrict__ A,
                             const float* __restrict__ B0, const float* __restrict__ B1,
                             const float* __restrict__ bias0, const float* __restrict__ bias1,
                             float* __restrict__ C0, float* __restrict__ C1,
                             int M, int Nn, int K, int act) {
    __shared__ float As[8][128];
    __shared__ float Bs[8][128];
    const int bx = blockIdx.x * 128;
    const int by = blockIdx.y * 128;
    const int z  = blockIdx.z;
    const float* B = z ? B1 : B0;
    const float* bias = z ? bias1 : bias0;
    float* C = z ? C1 : C0;
    const int tid = threadIdx.x;
    const int tr = tid / 16;
    const int tc = tid % 16;

    float acc[8][8];
#pragma unroll
    for (int i = 0; i < 8; i++)
#pragma unroll
        for (int j = 0; j < 8; j++) acc[i][j] = 0.f;

    const int row_a = tid / 2;
    const int cola0 = (tid % 2) * 4;
    const int row_b = tid / 32;
    const int colb0 = (tid % 32) * 4;

    for (int k0 = 0; k0 < K; k0 += 8) {
#pragma unroll
        for (int i = 0; i < 4; i++) {
            int r = by + row_a;
            int kk = k0 + cola0 + i;
            As[cola0 + i][row_a] = (r < M && kk < K) ? A[(size_t)r * K + kk] : 0.f;
        }
#pragma unroll
        for (int i = 0; i < 4; i++) {
            int kk = k0 + row_b;
            int c = bx + colb0 + i;
            Bs[row_b][colb0 + i] = (kk < K && c < Nn) ? B[(size_t)kk * Nn + c] : 0.f;
        }
        __syncthreads();
#pragma unroll
        for (int kk = 0; kk < 8; kk++) {
            float a[8], b[8];
#pragma unroll
            for (int i = 0; i < 8; i++) a[i] = As[kk][tr + 16 * i];
#pragma unroll
            for (int j = 0; j < 8; j++) b[j] = Bs[kk][tc + 16 * j];
#pragma unroll
            for (int i = 0; i < 8; i++)
#pragma unroll
                for (int j = 0; j < 8; j++) acc[i][j] += a[i] * b[j];
        }
        __syncthreads();
    }

#pragma unroll
    for (int i = 0; i < 8; i++) {
        int r = by + tr + 16 * i;
        if (r >= M) continue;
#pragma unroll
        for (int j = 0; j < 8; j++) {
            int c = bx + tc + 16 * j;
            if (c >= Nn) continue;
            float v = acc[i][j] + bias[c];
            if (act) v = (v > 0.f) ? v : 0.01f * v;
            C[(size_t)r * Nn + c] = v;
        }
    }
}

// ---------------- per-(edge,head) attention score (float4) ----------------
__global__ void score_kernel(const float* __restrict__ att, int C, int L) {
    int gw = (blockIdx.x * blockDim.x + threadIdx.x) >> 5;
    int lane = threadIdx.x & 31;
    if (gw >= ET * HH) return;
    int e = gw / HH, h = gw % HH;
    int s = g_src[e], d = g_dst[e];
    const int n4 = C >> 2;
    const float4* xl = (const float4*)(g_xl + ((size_t)s * HH + h) * C);
    const float4* xr = (const float4*)(g_xr + ((size_t)d * HH + h) * C);
    const float4* at = (const float4*)(att + h * C);
    float acc = 0.f;
    for (int c = lane; c < n4; c += 32) {
        float4 a = xl[c], b = xr[c], w = at[c];
        float v0 = a.x + b.x, v1 = a.y + b.y, v2 = a.z + b.z, v3 = a.w + b.w;
        v0 = (v0 > 0.f) ? v0 : 0.2f * v0;
        v1 = (v1 > 0.f) ? v1 : 0.2f * v1;
        v2 = (v2 > 0.f) ? v2 : 0.2f * v2;
        v3 = (v3 > 0.f) ? v3 : 0.2f * v3;
        acc += w.x * v0 + w.y * v1 + w.z * v2 + w.w * v3;
    }
#pragma unroll
    for (int o = 16; o; o >>= 1) acc += __shfl_xor_sync(0xffffffffu, acc, o);
    if (lane == 0) {
        g_score[e * HH + h] = acc;
        atomicMax(&g_smax[L * NN * HH + d * HH + h], flipf(acc));
    }
}

// ---------------- alpha = exp(score - max); accumulate denominators ----------------
__global__ void alpha_kernel(int L) {
    int i = blockIdx.x * blockDim.x + threadIdx.x;
    if (i >= ET * HH) return;
    int e = i / HH, h = i % HH;
    int d = g_dst[e];
    float m = unflipf(g_smax[L * NN * HH + d * HH + h]);
    float a = expf(g_score[i] - m);
    g_alpha[i] = a;
    atomicAdd(&g_denom[L * NN * HH + d * HH + h], a);
}

// ---------------- CSR aggregation + bias + optional lrelu; no atomics ----------------
__global__ void aggregate_kernel(const float* __restrict__ bias,
                                 float* __restrict__ out, int C, int L, int act) {
    const int n = blockIdx.x;
    const int c = blockIdx.y * 128 + threadIdx.x;
    const int tid = threadIdx.x;
    __shared__ float sw[64 * HH];
    __shared__ int   sid[64];
    const int r0 = g_rowptr[n], r1 = g_rowptr[n + 1];
    const float* dnm = g_denom + L * NN * HH + n * HH;
    float acc = 0.f;
    for (int r = r0; r < r1; r += 64) {
        int cd = min(64, r1 - r);
        __syncthreads();
        for (int i = tid; i < cd * HH; i += 128) {
            int le = i >> 5, h = i & 31;
            int e = g_eid[r + le];
            sw[i] = g_alpha[e * HH + h] / dnm[h] * (1.0f / HH);
        }
        if (tid < cd) sid[tid] = g_src[g_eid[r + tid]];
        __syncthreads();
        if (c < C) {
            for (int le = 0; le < cd; le++) {
                const float* xrow = g_xl + (size_t)sid[le] * HH * C + c;
                const float* wrow = sw + le * HH;
#pragma unroll 4
                for (int h = 0; h < HH; h++)
                    acc += wrow[h] * xrow[(size_t)h * C];
            }
        }
    }
    if (c < C) {
        float v = acc + bias[c];
        if (act) v = (v > 0.f) ? v : 0.01f * v;
        out[(size_t)n * C + c] = v;
    }
}

// ---------------- host-side orchestration ----------------
static __nv_bfloat16 *h_ah, *h_al, *h_bh0, *h_bl0, *h_bh1, *h_bl1;

static void convert_A(const float* A, int M, int K, int Kp) {
    int n4 = (M * Kp) >> 2;
    convertA_kernel<<<(n4 + 255) / 256, 256>>>(A, M, K, Kp);
}

static void run_tc_pair(const float* B0, const float* bias0, float* C0,
                        const float* B1, const float* bias1, float* C1,
                        int M, int Nn, int K, int Kp, int act, int nz) {
    int n4 = (Kp * Nn) >> 2;
    convertB_kernel<<<dim3((n4 + 255) / 256, nz), 256>>>(B0, B1 ? B1 : B0, K, Nn, Kp);
    cudaFuncSetAttribute(tc_gemm_kernel, cudaFuncAttributeMaxDynamicSharedMemorySize, DSMEM);
    dim3 grid(Nn / 128, M / 128, nz);
    tc_gemm_kernel<<<grid, 256, DSMEM>>>(h_ah, h_al, h_bh0, h_bl0, h_bh1, h_bl1,
                                         bias0, bias1 ? bias1 : bias0,
                                         C0, C1 ? C1 : C0, Nn, Kp, act);
}

static void gat_attention(const float* att, const float* gb, float* zout,
                          int Cout, int L, int act_after) {
    score_kernel<<<(ET * HH) / 8, 256>>>(att, Cout, L);
    alpha_kernel<<<(ET * HH + 255) / 256, 256>>>(L);
    aggregate_kernel<<<dim3(NN, (Cout + 127) / 128), 128>>>(gb, zout, Cout, L, act_after);
}

extern "C" void kernel_launch(void* const* d_in, const int* in_sizes, int n_in,
                              void* d_out, int out_size) {
    const float* x  = (const float*)d_in[0];
    const void*  ei = d_in[1];
    const float* w1l = (const float*)d_in[2];
    const float* b1l = (const float*)d_in[3];
    const float* w1r = (const float*)d_in[4];
    const float* b1r = (const float*)d_in[5];
    const float* att1 = (const float*)d_in[6];
    const float* gb1  = (const float*)d_in[7];
    const float* w2l = (const float*)d_in[8];
    const float* b2l = (const float*)d_in[9];
    const float* w2r = (const float*)d_in[10];
    const float* b2r = (const float*)d_in[11];
    const float* att2 = (const float*)d_in[12];
    const float* gb2  = (const float*)d_in[13];
    const float* w3l = (const float*)d_in[14];
    const float* b3l = (const float*)d_in[15];
    const float* w3r = (const float*)d_in[16];
    const float* b3r = (const float*)d_in[17];
    const float* att3 = (const float*)d_in[18];
    const float* gb3  = (const float*)d_in[19];
    const float* dw1 = (const float*)d_in[20];
    const float* db1 = (const float*)d_in[21];
    const float* dw2 = (const float*)d_in[22];
    const float* db2 = (const float*)d_in[23];
    const float* dw3 = (const float*)d_in[24];
    const float* db3 = (const float*)d_in[25];

    void* p;
    cudaGetSymbolAddress(&p, g_xl);   float* xl   = (float*)p;
    cudaGetSymbolAddress(&p, g_xr);   float* xr   = (float*)p;
    cudaGetSymbolAddress(&p, g_buf1); float* buf1 = (float*)p;
    cudaGetSymbolAddress(&p, g_buf2); float* buf2 = (float*)p;
    cudaGetSymbolAddress(&p, g_ah);   h_ah  = (__nv_bfloat16*)p;
    cudaGetSymbolAddress(&p, g_al);   h_al  = (__nv_bfloat16*)p;
    cudaGetSymbolAddress(&p, g_bh0);  h_bh0 = (__nv_bfloat16*)p;
    cudaGetSymbolAddress(&p, g_bl0);  h_bl0 = (__nv_bfloat16*)p;
    cudaGetSymbolAddress(&p, g_bh1);  h_bh1 = (__nv_bfloat16*)p;
    cudaGetSymbolAddress(&p, g_bl1);  h_bl1 = (__nv_bfloat16*)p;

    // edges (dtype-robust) + per-layer softmax state init + CSR
    detect_dtype_kernel<<<1, 256>>>(ei);
    build_edges_kernel<<<(3 * NN * HH + 255) / 256, 256>>>(ei);
    csr_rank_kernel<<<(ET + 255) / 256, 256>>>();
    csr_scan_kernel<<<1, NN>>>();
    csr_place_kernel<<<(ET + 255) / 256, 256>>>();

    // ---- GAT layer 1 (Cin=4, fp32 pair GEMM), Cout=128
    sgemm_kernel<<<dim3(32, 8, 2), 256>>>(x, w1l, w1r, b1l, b1r, xl, xr,
                                          NN, HH * 128, 4, 0);
    gat_attention(att1, gb1, buf1, 128, 0, 1);

    // ---- GAT layer 2: Cin=128, Cout=512
    convert_A(buf1, NN, 128, 128);
    run_tc_pair(w2l, b2l, xl, w2r, b2r, xr, NN, HH * 512, 128, 128, 0, 2);
    gat_attention(att2, gb2, buf2, 512, 1, 1);

    // ---- GAT layer 3: Cin=512, Cout=1028
    convert_A(buf2, NN, 512, 512);
    run_tc_pair(w3l, b3l, xl, w3r, b3r, xr, NN, HH * 1028, 512, 512, 0, 2);
    gat_attention(att3, gb3, buf1, 1028, 2, 0);

    // ---- decoder MLP
    convert_A(buf1, NN, 1028, 1088);
    run_tc_pair(dw1, db1, buf2, 0, 0, 0, NN, 512, 1028, 1088, 1, 1);
    convert_A(buf2, NN, 512, 512);
    run_tc_pair(dw2, db2, buf1, 0, 0, 0, NN, 128, 512, 512, 1, 1);
    sgemm_kernel<<<dim3(1, 8, 1), 256>>>(buf1, dw3, dw3, db3, db3,
                                         (float*)d_out, (float*)d_out,
                                         NN, 2, 128, 0);

    (void)in_sizes; (void)n_in; (void)out_size;
}

// round 7
// speedup vs baseline: 3.3356x; 1.2639x over previous
#include <cuda_runtime.h>
#include <cuda_fp16.h>
#include <cstdint>

#define NN   1024      // nodes
#define EE   2048      // raw edges
#define ET   3072      // edges + self loops
#define HH   32        // heads
#define CMX  1028      // max per-head channel dim
#define KPMX 1088      // max padded K
#define BMAX 16842752  // 32896*512 max weight elements

// ---------------- scratch (device globals; no allocation allowed) ----------------
__device__ float    g_xl[(size_t)NN * HH * CMX];
__device__ float    g_xr[(size_t)NN * HH * CMX];
__device__ float    g_buf1[NN * CMX];
__device__ float    g_buf2[NN * CMX];
__device__ float    g_score[ET * HH];
__device__ float    g_alpha[ET * HH];
__device__ unsigned g_smax[3 * NN * HH];
__device__ float    g_denom[3 * NN * HH];
__device__ int      g_src[ET];
__device__ int      g_dst[ET];
__device__ int      g_rank[ET];
__device__ int      g_deg[NN];
__device__ int      g_rowptr[NN + 1];
__device__ int      g_eid[ET];
__device__ int      g_is64;
__device__ __half   g_ah[NN * KPMX];
__device__ __half   g_al[NN * KPMX];
__device__ __half   g_b0[BMAX];
__device__ __half   g_b1[BMAX];

// ---------------- helpers ----------------
__device__ __forceinline__ unsigned flipf(float f) {
    unsigned u = __float_as_uint(f);
    return u ^ ((unsigned)((int)u >> 31) | 0x80000000u);
}
__device__ __forceinline__ float unflipf(unsigned v) {
    unsigned m = (v & 0x80000000u) ? 0x80000000u : 0xFFFFFFFFu;
    return __uint_as_float(v ^ m);
}

// ---------------- edge dtype detection ----------------
__global__ void detect_dtype_kernel(const void* ei) {
    __shared__ int bad;
    if (threadIdx.x == 0) bad = 0;
    __syncthreads();
    const long long* p = (const long long*)ei;
    for (int i = threadIdx.x; i < EE; i += blockDim.x) {
        long long v = p[i];
        if (v < 0 || v >= NN) bad = 1;
    }
    __syncthreads();
    if (threadIdx.x == 0) g_is64 = !bad;
}

// ---------------- edge build + softmax-state init + deg zero ----------------
__global__ void build_edges_kernel(const void* ei) {
    int i = blockIdx.x * blockDim.x + threadIdx.x;
    if (i < ET) {
        if (i < EE) {
            if (g_is64) {
                const long long* p = (const long long*)ei;
                g_src[i] = (int)p[i];
                g_dst[i] = (int)p[EE + i];
            } else {
                const int* p = (const int*)ei;
                g_src[i] = p[i];
                g_dst[i] = p[EE + i];
            }
        } else {
            g_src[i] = i - EE;
            g_dst[i] = i - EE;
        }
    }
    if (i < 3 * NN * HH) {
        g_smax[i] = 0u;
        g_denom[i] = 0.f;
    }
    if (i < NN) g_deg[i] = 0;
}

// ---------------- CSR build (deterministic) ----------------
__global__ void csr_rank_kernel() {
    __shared__ int sd[ET];
    int tid = threadIdx.x;
    for (int i = tid; i < ET; i += blockDim.x) sd[i] = g_dst[i];
    __syncthreads();
    int e = blockIdx.x * blockDim.x + tid;
    if (e < ET) {
        int d = sd[e], r = 0;
        for (int e2 = 0; e2 < e; e2++) r += (sd[e2] == d);
        g_rank[e] = r;
        atomicAdd(&g_deg[d], 1);
    }
}

__global__ void csr_scan_kernel() {
    __shared__ int s[NN];
    int t = threadIdx.x;
    s[t] = g_deg[t];
    __syncthreads();
    for (int o = 1; o < NN; o <<= 1) {
        int v = (t >= o) ? s[t - o] : 0;
        __syncthreads();
        s[t] += v;
        __syncthreads();
    }
    g_rowptr[t + 1] = s[t];
    if (t == 0) g_rowptr[0] = 0;
}

__global__ void csr_place_kernel() {
    int e = blockIdx.x * blockDim.x + threadIdx.x;
    if (e < ET) g_eid[g_rowptr[g_dst[e]] + g_rank[e]] = e;
}

// ---------------- fp32 -> fp16 hi/lo split (A: col pad, float4) ----------------
__global__ void convertA_kernel(const float* __restrict__ src,
                                int M, int K, int Kp) {
    int i4 = blockIdx.x * blockDim.x + threadIdx.x;
    int tot = (M * Kp) >> 2;
    if (i4 >= tot) return;
    int kp4 = Kp >> 2;
    int r = i4 / kp4, c4 = (i4 - r * kp4) << 2;
    float v[4];
    if (c4 + 3 < K) {
        float4 f = *(const float4*)(src + (size_t)r * K + c4);
        v[0] = f.x; v[1] = f.y; v[2] = f.z; v[3] = f.w;
    } else {
#pragma unroll
        for (int j = 0; j < 4; j++)
            v[j] = (c4 + j < K) ? src[(size_t)r * K + c4 + j] : 0.f;
    }
    __half2 h2[2], l2[2];
#pragma unroll
    for (int j = 0; j < 2; j++) {
        __half h0 = __float2half_rn(v[2 * j]);
        __half h1 = __float2half_rn(v[2 * j + 1]);
        h2[j] = __halves2half2(h0, h1);
        l2[j] = __halves2half2(__float2half_rn(v[2 * j] - __half2float(h0)),
                               __float2half_rn(v[2 * j + 1] - __half2float(h1)));
    }
    size_t o = (size_t)r * Kp + c4;
    *(__half2*)(g_ah + o)     = h2[0];
    *(__half2*)(g_ah + o + 2) = h2[1];
    *(__half2*)(g_al + o)     = l2[0];
    *(__half2*)(g_al + o + 2) = l2[1];
}

// ---------------- fp32 [K,Nn] -> fp16, row pad to Kp; pair fused via blockIdx.y ----------------
__global__ void convertB_kernel(const float* __restrict__ B0,
                                const float* __restrict__ B1,
                                int K, int Nn, int Kp) {
    int i4 = blockIdx.x * blockDim.x + threadIdx.x;
    int tot = (Kp * Nn) >> 2;
    if (i4 >= tot) return;
    const float* src = blockIdx.y ? B1 : B0;
    __half* dst = blockIdx.y ? g_b1 : g_b0;
    int n4 = Nn >> 2;
    int r = i4 / n4, c4 = (i4 - r * n4) << 2;
    float v[4];
    if (r < K) {
        float4 f = *(const float4*)(src + (size_t)r * Nn + c4);
        v[0] = f.x; v[1] = f.y; v[2] = f.z; v[3] = f.w;
    } else {
        v[0] = v[1] = v[2] = v[3] = 0.f;
    }
    size_t o = (size_t)r * Nn + c4;
    *(__half2*)(dst + o)     = __halves2half2(__float2half_rn(v[0]), __float2half_rn(v[1]));
    *(__half2*)(dst + o + 2) = __halves2half2(__float2half_rn(v[2]), __float2half_rn(v[3]));
}

// ---------------- tensor-core GEMM (fp16x2 split, fp32 accum, cp.async pipeline) ----------------
#define ASTR 40    // fp16 row stride, A tiles [128][32]
#define BSTR 136   // fp16 row stride, B tiles [32][128]
#define AHOFF 0
#define ALOFF 10240
#define BOFF  20480
#define BUFSZ 29184
#define DSMEM (2 * BUFSZ)

#define LDMX4(R0,R1,R2,R3,ADDR) \
    asm volatile("ldmatrix.sync.aligned.m8n8.x4.shared.b16 {%0,%1,%2,%3}, [%4];" \
        : "=r"(R0), "=r"(R1), "=r"(R2), "=r"(R3) : "r"(ADDR))
#define LDMX2T(R0,R1,ADDR) \
    asm volatile("ldmatrix.sync.aligned.m8n8.x2.trans.shared.b16 {%0,%1}, [%2];" \
        : "=r"(R0), "=r"(R1) : "r"(ADDR))
#define MMA16816(C0,C1,C2,C3,A0,A1,A2,A3,B0,B1) \
    asm volatile("mma.sync.aligned.m16n8k16.row.col.f32.f16.f16.f32 " \
        "{%0,%1,%2,%3}, {%4,%5,%6,%7}, {%8,%9}, {%0,%1,%2,%3};" \
        : "+f"(C0), "+f"(C1), "+f"(C2), "+f"(C3) \
        : "r"(A0), "r"(A1), "r"(A2), "r"(A3), "r"(B0), "r"(B1))
#define CP16(SADDR, GPTR) \
    asm volatile("cp.async.ca.shared.global [%0], [%1], 16;" :: "r"(SADDR), "l"(GPTR))

__global__ __launch_bounds__(256) void tc_gemm_kernel(
    const __half* __restrict__ Ah, const __half* __restrict__ Al,
    const __half* __restrict__ B0, const __half* __restrict__ B1,
    const float* __restrict__ bias0, const float* __restrict__ bias1,
    float* __restrict__ C0, float* __restrict__ C1,
    int Nn, int Kp, int act)
{
    extern __shared__ char smem[];
    const uint32_t sbase = (uint32_t)__cvta_generic_to_shared(smem);

    const int tid  = threadIdx.x;
    const int warp = tid >> 5;
    const int lane = tid & 31;
    const int wm = (warp >> 2) * 64;
    const int wn = (warp & 3) * 32;
    const int bx = blockIdx.x * 128;
    const int by = blockIdx.y * 128;
    const int z  = blockIdx.z;

    const __half* B = z ? B1 : B0;
    const float* bias = z ? bias1 : bias0;
    float* C = z ? C1 : C0;

    float acc[4][4][4];
#pragma unroll
    for (int mi = 0; mi < 4; mi++)
#pragma unroll
        for (int ni = 0; ni < 4; ni++)
#pragma unroll
            for (int k = 0; k < 4; k++) acc[mi][ni][k] = 0.f;

    const int nc = Kp >> 5;

    auto load_tile = [&](int c, int b) {
        const int k0 = c << 5;
        const uint32_t base = sbase + b * BUFSZ;
#pragma unroll
        for (int j = 0; j < 2; j++) {
            int idx = tid + j * 256;
            int row = idx >> 2, seg = idx & 3;
            size_t go = (size_t)(by + row) * Kp + k0 + seg * 8;
            uint32_t so = base + (uint32_t)(row * ASTR + seg * 8) * 2;
            CP16(so + AHOFF, Ah + go);
            CP16(so + ALOFF, Al + go);
        }
#pragma unroll
        for (int j = 0; j < 2; j++) {
            int idx = tid + j * 256;
            int row = idx >> 4, seg = idx & 15;
            size_t go = (size_t)(k0 + row) * Nn + bx + seg * 8;
            uint32_t so = base + (uint32_t)(row * BSTR + seg * 8) * 2;
            CP16(so + BOFF, B + go);
        }
        asm volatile("cp.async.commit_group;" ::: "memory");
    };

    const int r8 = lane & 7;
    const int gA = lane >> 3;
    const int gB = (lane >> 3) & 1;

    load_tile(0, 0);

    for (int c = 0; c < nc; c++) {
        const int b = c & 1;
        if (c + 1 < nc) {
            load_tile(c + 1, (c + 1) & 1);
            asm volatile("cp.async.wait_group 1;" ::: "memory");
        } else {
            asm volatile("cp.async.wait_group 0;" ::: "memory");
        }
        __syncthreads();

        const uint32_t base = sbase + b * BUFSZ;
#pragma unroll
        for (int ks = 0; ks < 2; ks++) {
            const int ko = ks * 16;
            uint32_t ah[4][4], al[4][4], bb[4][2];
#pragma unroll
            for (int mi = 0; mi < 4; mi++) {
                int row = wm + mi * 16 + r8 + (gA & 1) * 8;
                int col = ko + (gA >> 1) * 8;
                uint32_t off = (uint32_t)(row * ASTR + col) * 2;
                LDMX4(ah[mi][0], ah[mi][1], ah[mi][2], ah[mi][3], base + AHOFF + off);
                LDMX4(al[mi][0], al[mi][1], al[mi][2], al[mi][3], base + ALOFF + off);
            }
#pragma unroll
            for (int ni = 0; ni < 4; ni++) {
                int row = ko + gB * 8 + r8;
                int col = wn + ni * 8;
                uint32_t off = (uint32_t)(row * BSTR + col) * 2;
                LDMX2T(bb[ni][0], bb[ni][1], base + BOFF + off);
            }
#pragma unroll
            for (int mi = 0; mi < 4; mi++) {
#pragma unroll
                for (int ni = 0; ni < 4; ni++) {
                    float* cc = acc[mi][ni];
                    MMA16816(cc[0], cc[1], cc[2], cc[3],
                             ah[mi][0], ah[mi][1], ah[mi][2], ah[mi][3],
                             bb[ni][0], bb[ni][1]);
                    MMA16816(cc[0], cc[1], cc[2], cc[3],
                             al[mi][0], al[mi][1], al[mi][2], al[mi][3],
                             bb[ni][0], bb[ni][1]);
                }
            }
        }
        __syncthreads();
    }

    const int g = lane >> 2, tig = lane & 3;
#pragma unroll
    for (int mi = 0; mi < 4; mi++) {
#pragma unroll
        for (int ni = 0; ni < 4; ni++) {
            int row = by + wm + mi * 16 + g;
            int col = bx + wn + ni * 8 + tig * 2;
            float bv0 = bias[col], bv1 = bias[col + 1];
            float v0 = acc[mi][ni][0] + bv0;
            float v1 = acc[mi][ni][1] + bv1;
            float v2 = acc[mi][ni][2] + bv0;
            float v3 = acc[mi][ni][3] + bv1;
            if (act) {
                v0 = (v0 > 0.f) ? v0 : 0.01f * v0;
                v1 = (v1 > 0.f) ? v1 : 0.01f * v1;
                v2 = (v2 > 0.f) ? v2 : 0.01f * v2;
                v3 = (v3 > 0.f) ? v3 : 0.01f * v3;
            }
            C[(size_t)row * Nn + col]           = v0;
            C[(size_t)row * Nn + col + 1]       = v1;
            C[(size_t)(row + 8) * Nn + col]     = v2;
            C[(size_t)(row + 8) * Nn + col + 1] = v3;
        }
    }
}

// ---------------- fp32 SGEMM with z-pair fusion (K=4 layer-1; final N=2) ----------------
__global__ void sgemm_kernel(const float* __restrict__ A,
                             const float* __restrict__ B0, const float* __restrict__ B1,
                             const float* __restrict__ bias0, const float* __restrict__ bias1,
                             float* __restrict__ C0, float* __restrict__ C1,
                             int M, int Nn, int K, int act) {
    __shared__ float As[8][128];
    __shared__ float Bs[8][128];
    const int bx = blockIdx.x * 128;
    const int by = blockIdx.y * 128;
    const int z  = blockIdx.z;
    const float* B = z ? B1 : B0;
    const float* bias = z ? bias1 : bias0;
    float* C = z ? C1 : C0;
    const int tid = threadIdx.x;
    const int tr = tid / 16;
    const int tc = tid % 16;

    float acc[8][8];
#pragma unroll
    for (int i = 0; i < 8; i++)
#pragma unroll
        for (int j = 0; j < 8; j++) acc[i][j] = 0.f;

    const int row_a = tid / 2;
    const int cola0 = (tid % 2) * 4;
    const int row_b = tid / 32;
    const int colb0 = (tid % 32) * 4;

    for (int k0 = 0; k0 < K; k0 += 8) {
#pragma unroll
        for (int i = 0; i < 4; i++) {
            int r = by + row_a;
            int kk = k0 + cola0 + i;
            As[cola0 + i][row_a] = (r < M && kk < K) ? A[(size_t)r * K + kk] : 0.f;
        }
#pragma unroll
        for (int i = 0; i < 4; i++) {
            int kk = k0 + row_b;
            int c = bx + colb0 + i;
            Bs[row_b][colb0 + i] = (kk < K && c < Nn) ? B[(size_t)kk * Nn + c] : 0.f;
        }
        __syncthreads();
#pragma unroll
        for (int kk = 0; kk < 8; kk++) {
            float a[8], b[8];
#pragma unroll
            for (int i = 0; i < 8; i++) a[i] = As[kk][tr + 16 * i];
#pragma unroll
            for (int j = 0; j < 8; j++) b[j] = Bs[kk][tc + 16 * j];
#pragma unroll
            for (int i = 0; i < 8; i++)
#pragma unroll
                for (int j = 0; j < 8; j++) acc[i][j] += a[i] * b[j];
        }
        __syncthreads();
    }

#pragma unroll
    for (int i = 0; i < 8; i++) {
        int r = by + tr + 16 * i;
        if (r >= M) continue;
#pragma unroll
        for (int j = 0; j < 8; j++) {
            int c = bx + tc + 16 * j;
            if (c >= Nn) continue;
            float v = acc[i][j] + bias[c];
            if (act) v = (v > 0.f) ? v : 0.01f * v;
            C[(size_t)r * Nn + c] = v;
        }
    }
}

// ---------------- per-(edge,head) attention score (float4) ----------------
__global__ void score_kernel(const float* __restrict__ att, int C, int L) {
    int gw = (blockIdx.x * blockDim.x + threadIdx.x) >> 5;
    int lane = threadIdx.x & 31;
    if (gw >= ET * HH) return;
    int e = gw / HH, h = gw % HH;
    int s = g_src[e], d = g_dst[e];
    const int n4 = C >> 2;
    const float4* xl = (const float4*)(g_xl + ((size_t)s * HH + h) * C);
    const float4* xr = (const float4*)(g_xr + ((size_t)d * HH + h) * C);
    const float4* at = (const float4*)(att + h * C);
    float acc = 0.f;
    for (int c = lane; c < n4; c += 32) {
        float4 a = xl[c], b = xr[c], w = at[c];
        float v0 = a.x + b.x, v1 = a.y + b.y, v2 = a.z + b.z, v3 = a.w + b.w;
        v0 = (v0 > 0.f) ? v0 : 0.2f * v0;
        v1 = (v1 > 0.f) ? v1 : 0.2f * v1;
        v2 = (v2 > 0.f) ? v2 : 0.2f * v2;
        v3 = (v3 > 0.f) ? v3 : 0.2f * v3;
        acc += w.x * v0 + w.y * v1 + w.z * v2 + w.w * v3;
    }
#pragma unroll
    for (int o = 16; o; o >>= 1) acc += __shfl_xor_sync(0xffffffffu, acc, o);
    if (lane == 0) {
        g_score[e * HH + h] = acc;
        atomicMax(&g_smax[L * NN * HH + d * HH + h], flipf(acc));
    }
}

// ---------------- alpha = exp(score - max); accumulate denominators ----------------
__global__ void alpha_kernel(int L) {
    int i = blockIdx.x * blockDim.x + threadIdx.x;
    if (i >= ET * HH) return;
    int e = i / HH, h = i % HH;
    int d = g_dst[e];
    float m = unflipf(g_smax[L * NN * HH + d * HH + h]);
    float a = expf(g_score[i] - m);
    g_alpha[i] = a;
    atomicAdd(&g_denom[L * NN * HH + d * HH + h], a);
}

// ---------------- CSR aggregation + bias + optional lrelu; no atomics ----------------
__global__ void aggregate_kernel(const float* __restrict__ bias,
                                 float* __restrict__ out, int C, int L, int act) {
    const int n = blockIdx.x;
    const int c = blockIdx.y * 128 + threadIdx.x;
    const int tid = threadIdx.x;
    __shared__ float sw[64 * HH];
    __shared__ int   sid[64];
    const int r0 = g_rowptr[n], r1 = g_rowptr[n + 1];
    const float* dnm = g_denom + L * NN * HH + n * HH;
    float acc = 0.f;
    for (int r = r0; r < r1; r += 64) {
        int cd = min(64, r1 - r);
        __syncthreads();
        for (int i = tid; i < cd * HH; i += 128) {
            int le = i >> 5, h = i & 31;
            int e = g_eid[r + le];
            sw[i] = g_alpha[e * HH + h] / dnm[h] * (1.0f / HH);
        }
        if (tid < cd) sid[tid] = g_src[g_eid[r + tid]];
        __syncthreads();
        if (c < C) {
            for (int le = 0; le < cd; le++) {
                const float* xrow = g_xl + (size_t)sid[le] * HH * C + c;
                const float* wrow = sw + le * HH;
#pragma unroll 4
                for (int h = 0; h < HH; h++)
                    acc += wrow[h] * xrow[(size_t)h * C];
            }
        }
    }
    if (c < C) {
        float v = acc + bias[c];
        if (act) v = (v > 0.f) ? v : 0.01f * v;
        out[(size_t)n * C + c] = v;
    }
}

// ---------------- host-side orchestration ----------------
static __half *h_ah, *h_al, *h_b0, *h_b1;

static void convert_A(const float* A, int M, int K, int Kp) {
    int n4 = (M * Kp) >> 2;
    convertA_kernel<<<(n4 + 255) / 256, 256>>>(A, M, K, Kp);
}

static void run_tc_pair(const float* B0, const float* bias0, float* C0,
                        const float* B1, const float* bias1, float* C1,
                        int M, int Nn, int K, int Kp, int act, int nz) {
    int n4 = (Kp * Nn) >> 2;
    convertB_kernel<<<dim3((n4 + 255) / 256, nz), 256>>>(B0, B1 ? B1 : B0, K, Nn, Kp);
    cudaFuncSetAttribute(tc_gemm_kernel, cudaFuncAttributeMaxDynamicSharedMemorySize, DSMEM);
    dim3 grid(Nn / 128, M / 128, nz);
    tc_gemm_kernel<<<grid, 256, DSMEM>>>(h_ah, h_al, h_b0, h_b1,
                                         bias0, bias1 ? bias1 : bias0,
                                         C0, C1 ? C1 : C0, Nn, Kp, act);
}

static void gat_attention(const float* att, const float* gb, float* zout,
                          int Cout, int L, int act_after) {
    score_kernel<<<(ET * HH) / 8, 256>>>(att, Cout, L);
    alpha_kernel<<<(ET * HH + 255) / 256, 256>>>(L);
    aggregate_kernel<<<dim3(NN, (Cout + 127) / 128), 128>>>(gb, zout, Cout, L, act_after);
}

extern "C" void kernel_launch(void* const* d_in, const int* in_sizes, int n_in,
                              void* d_out, int out_size) {
    const float* x  = (const float*)d_in[0];
    const void*  ei = d_in[1];
    const float* w1l = (const float*)d_in[2];
    const float* b1l = (const float*)d_in[3];
    const float* w1r = (const float*)d_in[4];
    const float* b1r = (const float*)d_in[5];
    const float* att1 = (const float*)d_in[6];
    const float* gb1  = (const float*)d_in[7];
    const float* w2l = (const float*)d_in[8];
    const float* b2l = (const float*)d_in[9];
    const float* w2r = (const float*)d_in[10];
    const float* b2r = (const float*)d_in[11];
    const float* att2 = (const float*)d_in[12];
    const float* gb2  = (const float*)d_in[13];
    const float* w3l = (const float*)d_in[14];
    const float* b3l = (const float*)d_in[15];
    const float* w3r = (const float*)d_in[16];
    const float* b3r = (const float*)d_in[17];
    const float* att3 = (const float*)d_in[18];
    const float* gb3  = (const float*)d_in[19];
    const float* dw1 = (const float*)d_in[20];
    const float* db1 = (const float*)d_in[21];
    const float* dw2 = (const float*)d_in[22];
    const float* db2 = (const float*)d_in[23];
    const float* dw3 = (const float*)d_in[24];
    const float* db3 = (const float*)d_in[25];

    void* p;
    cudaGetSymbolAddress(&p, g_xl);   float* xl   = (float*)p;
    cudaGetSymbolAddress(&p, g_xr);   float* xr   = (float*)p;
    cudaGetSymbolAddress(&p, g_buf1); float* buf1 = (float*)p;
    cudaGetSymbolAddress(&p, g_buf2); float* buf2 = (float*)p;
    cudaGetSymbolAddress(&p, g_ah);   h_ah = (__half*)p;
    cudaGetSymbolAddress(&p, g_al);   h_al = (__half*)p;
    cudaGetSymbolAddress(&p, g_b0);   h_b0 = (__half*)p;
    cudaGetSymbolAddress(&p, g_b1);   h_b1 = (__half*)p;

    // edges (dtype-robust) + per-layer softmax state init + CSR
    detect_dtype_kernel<<<1, 256>>>(ei);
    build_edges_kernel<<<(3 * NN * HH + 255) / 256, 256>>>(ei);
    csr_rank_kernel<<<(ET + 255) / 256, 256>>>();
    csr_scan_kernel<<<1, NN>>>();
    csr_place_kernel<<<(ET + 255) / 256, 256>>>();

    // ---- GAT layer 1 (Cin=4, fp32 pair GEMM), Cout=128
    sgemm_kernel<<<dim3(32, 8, 2), 256>>>(x, w1l, w1r, b1l, b1r, xl, xr,
                                          NN, HH * 128, 4, 0);
    gat_attention(att1, gb1, buf1, 128, 0, 1);

    // ---- GAT layer 2: Cin=128, Cout=512
    convert_A(buf1, NN, 128, 128);
    run_tc_pair(w2l, b2l, xl, w2r, b2r, xr, NN, HH * 512, 128, 128, 0, 2);
    gat_attention(att2, gb2, buf2, 512, 1, 1);

    // ---- GAT layer 3: Cin=512, Cout=1028
    convert_A(buf2, NN, 512, 512);
    run_tc_pair(w3l, b3l, xl, w3r, b3r, xr, NN, HH * 1028, 512, 512, 0, 2);
    gat_attention(att3, gb3, buf1, 1028, 2, 0);

    // ---- decoder MLP
    convert_A(buf1, NN, 1028, 1088);
    run_tc_pair(dw1, db1, buf2, 0, 0, 0, NN, 512, 1028, 1088, 1, 1);
    convert_A(buf2, NN, 512, 512);
    run_tc_pair(dw2, db2, buf1, 0, 0, 0, NN, 128, 512, 512, 1, 1);
    sgemm_kernel<<<dim3(1, 8, 1), 256>>>(buf1, dw3, dw3, db3, db3,
                                         (float*)d_out, (float*)d_out,
                                         NN, 2, 128, 0);

    (void)in_sizes; (void)n_in; (void)out_size;
}

// round 8
// speedup vs baseline: 4.1328x; 1.2390x over previous
#include <cuda_runtime.h>
#include <cuda_fp16.h>
#include <cstdint>

#define NN   1024      // nodes
#define EE   2048      // raw edges
#define ET   3072      // edges + self loops
#define HH   32        // heads
#define CMX  1028      // max per-head channel dim
#define KPMX 1088      // max padded K
#define BMAX 16842752  // 32896*512 max weight elements

// ---------------- scratch (device globals; no allocation allowed) ----------------
__device__ float    g_xl[(size_t)NN * HH * CMX];
__device__ float    g_xr[(size_t)NN * HH * CMX];
__device__ float    g_buf1[NN * CMX];
__device__ float    g_buf2[NN * CMX];
__device__ float    g_score[ET * HH];
__device__ float    g_alpha[ET * HH];
__device__ unsigned g_smax[3 * NN * HH];
__device__ float    g_denom[3 * NN * HH];
__device__ int      g_src[ET];
__device__ int      g_dst[ET];
__device__ int      g_rank[ET];
__device__ int      g_deg[NN];
__device__ int      g_rowptr[NN + 1];
__device__ int      g_eid[ET];
__device__ int      g_is64;
__device__ __half   g_ah[NN * KPMX];
__device__ __half   g_b0[BMAX];
__device__ __half   g_b1[BMAX];

// ---------------- helpers ----------------
__device__ __forceinline__ unsigned flipf(float f) {
    unsigned u = __float_as_uint(f);
    return u ^ ((unsigned)((int)u >> 31) | 0x80000000u);
}
__device__ __forceinline__ float unflipf(unsigned v) {
    unsigned m = (v & 0x80000000u) ? 0x80000000u : 0xFFFFFFFFu;
    return __uint_as_float(v ^ m);
}

// ---------------- edge dtype detection ----------------
__global__ void detect_dtype_kernel(const void* ei) {
    __shared__ int bad;
    if (threadIdx.x == 0) bad = 0;
    __syncthreads();
    const long long* p = (const long long*)ei;
    for (int i = threadIdx.x; i < EE; i += blockDim.x) {
        long long v = p[i];
        if (v < 0 || v >= NN) bad = 1;
    }
    __syncthreads();
    if (threadIdx.x == 0) g_is64 = !bad;
}

// ---------------- edge build + softmax-state init + deg zero ----------------
__global__ void build_edges_kernel(const void* ei) {
    int i = blockIdx.x * blockDim.x + threadIdx.x;
    if (i < ET) {
        if (i < EE) {
            if (g_is64) {
                const long long* p = (const long long*)ei;
                g_src[i] = (int)p[i];
                g_dst[i] = (int)p[EE + i];
            } else {
                const int* p = (const int*)ei;
                g_src[i] = p[i];
                g_dst[i] = p[EE + i];
            }
        } else {
            g_src[i] = i - EE;
            g_dst[i] = i - EE;
        }
    }
    if (i < 3 * NN * HH) {
        g_smax[i] = 0u;
        g_denom[i] = 0.f;
    }
    if (i < NN) g_deg[i] = 0;
}

// ---------------- CSR build (deterministic) ----------------
__global__ void csr_rank_kernel() {
    __shared__ int sd[ET];
    int tid = threadIdx.x;
    for (int i = tid; i < ET; i += blockDim.x) sd[i] = g_dst[i];
    __syncthreads();
    int e = blockIdx.x * blockDim.x + tid;
    if (e < ET) {
        int d = sd[e], r = 0;
        for (int e2 = 0; e2 < e; e2++) r += (sd[e2] == d);
        g_rank[e] = r;
        atomicAdd(&g_deg[d], 1);
    }
}

__global__ void csr_scan_kernel() {
    __shared__ int s[NN];
    int t = threadIdx.x;
    s[t] = g_deg[t];
    __syncthreads();
    for (int o = 1; o < NN; o <<= 1) {
        int v = (t >= o) ? s[t - o] : 0;
        __syncthreads();
        s[t] += v;
        __syncthreads();
    }
    g_rowptr[t + 1] = s[t];
    if (t == 0) g_rowptr[0] = 0;
}

__global__ void csr_place_kernel() {
    int e = blockIdx.x * blockDim.x + threadIdx.x;
    if (e < ET) g_eid[g_rowptr[g_dst[e]] + g_rank[e]] = e;
}

// ---------------- fp32 -> fp16 (A: col pad, float4) ----------------
__global__ void convertA_kernel(const float* __restrict__ src,
                                int M, int K, int Kp) {
    int i4 = blockIdx.x * blockDim.x + threadIdx.x;
    int tot = (M * Kp) >> 2;
    if (i4 >= tot) return;
    int kp4 = Kp >> 2;
    int r = i4 / kp4, c4 = (i4 - r * kp4) << 2;
    float v[4];
    if (c4 + 3 < K) {
        float4 f = *(const float4*)(src + (size_t)r * K + c4);
        v[0] = f.x; v[1] = f.y; v[2] = f.z; v[3] = f.w;
    } else {
#pragma unroll
        for (int j = 0; j < 4; j++)
            v[j] = (c4 + j < K) ? src[(size_t)r * K + c4 + j] : 0.f;
    }
    size_t o = (size_t)r * Kp + c4;
    *(__half2*)(g_ah + o)     = __halves2half2(__float2half_rn(v[0]), __float2half_rn(v[1]));
    *(__half2*)(g_ah + o + 2) = __halves2half2(__float2half_rn(v[2]), __float2half_rn(v[3]));
}

// ---------------- fp32 [K,Nn] -> fp16, row pad to Kp; pair fused via blockIdx.y ----------------
__global__ void convertB_kernel(const float* __restrict__ B0,
                                const float* __restrict__ B1,
                                int K, int Nn, int Kp) {
    int i4 = blockIdx.x * blockDim.x + threadIdx.x;
    int tot = (Kp * Nn) >> 2;
    if (i4 >= tot) return;
    const float* src = blockIdx.y ? B1 : B0;
    __half* dst = blockIdx.y ? g_b1 : g_b0;
    int n4 = Nn >> 2;
    int r = i4 / n4, c4 = (i4 - r * n4) << 2;
    float v[4];
    if (r < K) {
        float4 f = *(const float4*)(src + (size_t)r * Nn + c4);
        v[0] = f.x; v[1] = f.y; v[2] = f.z; v[3] = f.w;
    } else {
        v[0] = v[1] = v[2] = v[3] = 0.f;
    }
    size_t o = (size_t)r * Nn + c4;
    *(__half2*)(dst + o)     = __halves2half2(__float2half_rn(v[0]), __float2half_rn(v[1]));
    *(__half2*)(dst + o + 2) = __halves2half2(__float2half_rn(v[2]), __float2half_rn(v[3]));
}

// ---------------- tensor-core GEMM (plain fp16, fp32 accum, cp.async pipeline) ----------------
// C[M,Nn] = A[M,Kp] @ B[Kp,Nn] + bias, optional leakyrelu(0.01).
// M%128==0, Nn%128==0, Kp%32==0. BM=BN=128, BK=32, 256 threads.
#define ASTR 40    // fp16 row stride, A tile [128][32]
#define BSTR 136   // fp16 row stride, B tile [32][128]
#define AOFF 0
#define BOFF 10240
#define BUFSZ 18944
#define DSMEM (2 * BUFSZ)

#define LDMX4(R0,R1,R2,R3,ADDR) \
    asm volatile("ldmatrix.sync.aligned.m8n8.x4.shared.b16 {%0,%1,%2,%3}, [%4];" \
        : "=r"(R0), "=r"(R1), "=r"(R2), "=r"(R3) : "r"(ADDR))
#define LDMX2T(R0,R1,ADDR) \
    asm volatile("ldmatrix.sync.aligned.m8n8.x2.trans.shared.b16 {%0,%1}, [%2];" \
        : "=r"(R0), "=r"(R1) : "r"(ADDR))
#define MMA16816(C0,C1,C2,C3,A0,A1,A2,A3,B0,B1) \
    asm volatile("mma.sync.aligned.m16n8k16.row.col.f32.f16.f16.f32 " \
        "{%0,%1,%2,%3}, {%4,%5,%6,%7}, {%8,%9}, {%0,%1,%2,%3};" \
        : "+f"(C0), "+f"(C1), "+f"(C2), "+f"(C3) \
        : "r"(A0), "r"(A1), "r"(A2), "r"(A3), "r"(B0), "r"(B1))
#define CP16(SADDR, GPTR) \
    asm volatile("cp.async.ca.shared.global [%0], [%1], 16;" :: "r"(SADDR), "l"(GPTR))

__global__ __launch_bounds__(256) void tc_gemm_kernel(
    const __half* __restrict__ Ah,
    const __half* __restrict__ B0, const __half* __restrict__ B1,
    const float* __restrict__ bias0, const float* __restrict__ bias1,
    float* __restrict__ C0, float* __restrict__ C1,
    int Nn, int Kp, int act)
{
    extern __shared__ char smem[];
    const uint32_t sbase = (uint32_t)__cvta_generic_to_shared(smem);

    const int tid  = threadIdx.x;
    const int warp = tid >> 5;
    const int lane = tid & 31;
    const int wm = (warp >> 2) * 64;
    const int wn = (warp & 3) * 32;
    const int bx = blockIdx.x * 128;
    const int by = blockIdx.y * 128;
    const int z  = blockIdx.z;

    const __half* B = z ? B1 : B0;
    const float* bias = z ? bias1 : bias0;
    float* C = z ? C1 : C0;

    float acc[4][4][4];
#pragma unroll
    for (int mi = 0; mi < 4; mi++)
#pragma unroll
        for (int ni = 0; ni < 4; ni++)
#pragma unroll
            for (int k = 0; k < 4; k++) acc[mi][ni][k] = 0.f;

    const int nc = Kp >> 5;

    auto load_tile = [&](int c, int b) {
        const int k0 = c << 5;
        const uint32_t base = sbase + b * BUFSZ;
#pragma unroll
        for (int j = 0; j < 2; j++) {
            int idx = tid + j * 256;
            int row = idx >> 2, seg = idx & 3;
            size_t go = (size_t)(by + row) * Kp + k0 + seg * 8;
            uint32_t so = base + (uint32_t)(row * ASTR + seg * 8) * 2;
            CP16(so + AOFF, Ah + go);
        }
#pragma unroll
        for (int j = 0; j < 2; j++) {
            int idx = tid + j * 256;
            int row = idx >> 4, seg = idx & 15;
            size_t go = (size_t)(k0 + row) * Nn + bx + seg * 8;
            uint32_t so = base + (uint32_t)(row * BSTR + seg * 8) * 2;
            CP16(so + BOFF, B + go);
        }
        asm volatile("cp.async.commit_group;" ::: "memory");
    };

    const int r8 = lane & 7;
    const int gA = lane >> 3;
    const int gB = (lane >> 3) & 1;

    load_tile(0, 0);

    for (int c = 0; c < nc; c++) {
        const int b = c & 1;
        if (c + 1 < nc) {
            load_tile(c + 1, (c + 1) & 1);
            asm volatile("cp.async.wait_group 1;" ::: "memory");
        } else {
            asm volatile("cp.async.wait_group 0;" ::: "memory");
        }
        __syncthreads();

        const uint32_t base = sbase + b * BUFSZ;
#pragma unroll
        for (int ks = 0; ks < 2; ks++) {
            const int ko = ks * 16;
            uint32_t ah[4][4], bb[4][2];
#pragma unroll
            for (int mi = 0; mi < 4; mi++) {
                int row = wm + mi * 16 + r8 + (gA & 1) * 8;
                int col = ko + (gA >> 1) * 8;
                uint32_t off = (uint32_t)(row * ASTR + col) * 2;
                LDMX4(ah[mi][0], ah[mi][1], ah[mi][2], ah[mi][3], base + AOFF + off);
            }
#pragma unroll
            for (int ni = 0; ni < 4; ni++) {
                int row = ko + gB * 8 + r8;
                int col = wn + ni * 8;
                uint32_t off = (uint32_t)(row * BSTR + col) * 2;
                LDMX2T(bb[ni][0], bb[ni][1], base + BOFF + off);
            }
#pragma unroll
            for (int mi = 0; mi < 4; mi++) {
#pragma unroll
                for (int ni = 0; ni < 4; ni++) {
                    float* cc = acc[mi][ni];
                    MMA16816(cc[0], cc[1], cc[2], cc[3],
                             ah[mi][0], ah[mi][1], ah[mi][2], ah[mi][3],
                             bb[ni][0], bb[ni][1]);
                }
            }
        }
        __syncthreads();
    }

    const int g = lane >> 2, tig = lane & 3;
#pragma unroll
    for (int mi = 0; mi < 4; mi++) {
#pragma unroll
        for (int ni = 0; ni < 4; ni++) {
            int row = by + wm + mi * 16 + g;
            int col = bx + wn + ni * 8 + tig * 2;
            float bv0 = bias[col], bv1 = bias[col + 1];
            float v0 = acc[mi][ni][0] + bv0;
            float v1 = acc[mi][ni][1] + bv1;
            float v2 = acc[mi][ni][2] + bv0;
            float v3 = acc[mi][ni][3] + bv1;
            if (act) {
                v0 = (v0 > 0.f) ? v0 : 0.01f * v0;
                v1 = (v1 > 0.f) ? v1 : 0.01f * v1;
                v2 = (v2 > 0.f) ? v2 : 0.01f * v2;
                v3 = (v3 > 0.f) ? v3 : 0.01f * v3;
            }
            C[(size_t)row * Nn + col]           = v0;
            C[(size_t)row * Nn + col + 1]       = v1;
            C[(size_t)(row + 8) * Nn + col]     = v2;
            C[(size_t)(row + 8) * Nn + col + 1] = v3;
        }
    }
}

// ---------------- fp32 SGEMM with z-pair fusion (K=4 layer-1; final N=2) ----------------
__global__ void sgemm_kernel(const float* __restrict__ A,
                             const float* __restrict__ B0, const float* __restrict__ B1,
                             const float* __restrict__ bias0, const float* __restrict__ bias1,
                             float* __restrict__ C0, float* __restrict__ C1,
                             int M, int Nn, int K, int act) {
    __shared__ float As[8][128];
    __shared__ float Bs[8][128];
    const int bx = blockIdx.x * 128;
    const int by = blockIdx.y * 128;
    const int z  = blockIdx.z;
    const float* B = z ? B1 : B0;
    const float* bias = z ? bias1 : bias0;
    float* C = z ? C1 : C0;
    const int tid = threadIdx.x;
    const int tr = tid / 16;
    const int tc = tid % 16;

    float acc[8][8];
#pragma unroll
    for (int i = 0; i < 8; i++)
#pragma unroll
        for (int j = 0; j < 8; j++) acc[i][j] = 0.f;

    const int row_a = tid / 2;
    const int cola0 = (tid % 2) * 4;
    const int row_b = tid / 32;
    const int colb0 = (tid % 32) * 4;

    for (int k0 = 0; k0 < K; k0 += 8) {
#pragma unroll
        for (int i = 0; i < 4; i++) {
            int r = by + row_a;
            int kk = k0 + cola0 + i;
            As[cola0 + i][row_a] = (r < M && kk < K) ? A[(size_t)r * K + kk] : 0.f;
        }
#pragma unroll
        for (int i = 0; i < 4; i++) {
            int kk = k0 + row_b;
            int c = bx + colb0 + i;
            Bs[row_b][colb0 + i] = (kk < K && c < Nn) ? B[(size_t)kk * Nn + c] : 0.f;
        }
        __syncthreads();
#pragma unroll
        for (int kk = 0; kk < 8; kk++) {
            float a[8], b[8];
#pragma unroll
            for (int i = 0; i < 8; i++) a[i] = As[kk][tr + 16 * i];
#pragma unroll
            for (int j = 0; j < 8; j++) b[j] = Bs[kk][tc + 16 * j];
#pragma unroll
            for (int i = 0; i < 8; i++)
#pragma unroll
                for (int j = 0; j < 8; j++) acc[i][j] += a[i] * b[j];
        }
        __syncthreads();
    }

#pragma unroll
    for (int i = 0; i < 8; i++) {
        int r = by + tr + 16 * i;
        if (r >= M) continue;
#pragma unroll
        for (int j = 0; j < 8; j++) {
            int c = bx + tc + 16 * j;
            if (c >= Nn) continue;
            float v = acc[i][j] + bias[c];
            if (act) v = (v > 0.f) ? v : 0.01f * v;
            C[(size_t)r * Nn + c] = v;
        }
    }
}

// ---------------- per-(edge,head) attention score (float4) ----------------
__global__ void score_kernel(const float* __restrict__ att, int C, int L) {
    int gw = (blockIdx.x * blockDim.x + threadIdx.x) >> 5;
    int lane = threadIdx.x & 31;
    if (gw >= ET * HH) return;
    int e = gw / HH, h = gw % HH;
    int s = g_src[e], d = g_dst[e];
    const int n4 = C >> 2;
    const float4* xl = (const float4*)(g_xl + ((size_t)s * HH + h) * C);
    const float4* xr = (const float4*)(g_xr + ((size_t)d * HH + h) * C);
    const float4* at = (const float4*)(att + h * C);
    float acc = 0.f;
    for (int c = lane; c < n4; c += 32) {
        float4 a = xl[c], b = xr[c], w = at[c];
        float v0 = a.x + b.x, v1 = a.y + b.y, v2 = a.z + b.z, v3 = a.w + b.w;
        v0 = (v0 > 0.f) ? v0 : 0.2f * v0;
        v1 = (v1 > 0.f) ? v1 : 0.2f * v1;
        v2 = (v2 > 0.f) ? v2 : 0.2f * v2;
        v3 = (v3 > 0.f) ? v3 : 0.2f * v3;
        acc += w.x * v0 + w.y * v1 + w.z * v2 + w.w * v3;
    }
#pragma unroll
    for (int o = 16; o; o >>= 1) acc += __shfl_xor_sync(0xffffffffu, acc, o);
    if (lane == 0) {
        g_score[e * HH + h] = acc;
        atomicMax(&g_smax[L * NN * HH + d * HH + h], flipf(acc));
    }
}

// ---------------- alpha = exp(score - max); accumulate denominators ----------------
__global__ void alpha_kernel(int L) {
    int i = blockIdx.x * blockDim.x + threadIdx.x;
    if (i >= ET * HH) return;
    int e = i / HH, h = i % HH;
    int d = g_dst[e];
    float m = unflipf(g_smax[L * NN * HH + d * HH + h]);
    float a = expf(g_score[i] - m);
    g_alpha[i] = a;
    atomicAdd(&g_denom[L * NN * HH + d * HH + h], a);
}

// ---------------- CSR aggregation + bias + optional lrelu; no atomics ----------------
__global__ void aggregate_kernel(const float* __restrict__ bias,
                                 float* __restrict__ out, int C, int L, int act) {
    const int n = blockIdx.x;
    const int c = blockIdx.y * 128 + threadIdx.x;
    const int tid = threadIdx.x;
    __shared__ float sw[64 * HH];
    __shared__ int   sid[64];
    const int r0 = g_rowptr[n], r1 = g_rowptr[n + 1];
    const float* dnm = g_denom + L * NN * HH + n * HH;
    float acc = 0.f;
    for (int r = r0; r < r1; r += 64) {
        int cd = min(64, r1 - r);
        __syncthreads();
        for (int i = tid; i < cd * HH; i += 128) {
            int le = i >> 5, h = i & 31;
            int e = g_eid[r + le];
            sw[i] = g_alpha[e * HH + h] / dnm[h] * (1.0f / HH);
        }
        if (tid < cd) sid[tid] = g_src[g_eid[r + tid]];
        __syncthreads();
        if (c < C) {
            for (int le = 0; le < cd; le++) {
                const float* xrow = g_xl + (size_t)sid[le] * HH * C + c;
                const float* wrow = sw + le * HH;
#pragma unroll 4
                for (int h = 0; h < HH; h++)
                    acc += wrow[h] * xrow[(size_t)h * C];
            }
        }
    }
    if (c < C) {
        float v = acc + bias[c];
        if (act) v = (v > 0.f) ? v : 0.01f * v;
        out[(size_t)n * C + c] = v;
    }
}

// ---------------- host-side orchestration ----------------
static __half *h_ah, *h_b0, *h_b1;

static void convert_A(const float* A, int M, int K, int Kp) {
    int n4 = (M * Kp) >> 2;
    convertA_kernel<<<(n4 + 255) / 256, 256>>>(A, M, K, Kp);
}

static void run_tc_pair(const float* B0, const float* bias0, float* C0,
                        const float* B1, const float* bias1, float* C1,
                        int M, int Nn, int K, int Kp, int act, int nz) {
    int n4 = (Kp * Nn) >> 2;
    convertB_kernel<<<dim3((n4 + 255) / 256, nz), 256>>>(B0, B1 ? B1 : B0, K, Nn, Kp);
    cudaFuncSetAttribute(tc_gemm_kernel, cudaFuncAttributeMaxDynamicSharedMemorySize, DSMEM);
    dim3 grid(Nn / 128, M / 128, nz);
    tc_gemm_kernel<<<grid, 256, DSMEM>>>(h_ah, h_b0, h_b1,
                                         bias0, bias1 ? bias1 : bias0,
                                         C0, C1 ? C1 : C0, Nn, Kp, act);
}

static void gat_attention(const float* att, const float* gb, float* zout,
                          int Cout, int L, int act_after) {
    score_kernel<<<(ET * HH) / 8, 256>>>(att, Cout, L);
    alpha_kernel<<<(ET * HH + 255) / 256, 256>>>(L);
    aggregate_kernel<<<dim3(NN, (Cout + 127) / 128), 128>>>(gb, zout, Cout, L, act_after);
}

extern "C" void kernel_launch(void* const* d_in, const int* in_sizes, int n_in,
                              void* d_out, int out_size) {
    const float* x  = (const float*)d_in[0];
    const void*  ei = d_in[1];
    const float* w1l = (const float*)d_in[2];
    const float* b1l = (const float*)d_in[3];
    const float* w1r = (const float*)d_in[4];
    const float* b1r = (const float*)d_in[5];
    const float* att1 = (const float*)d_in[6];
    const float* gb1  = (const float*)d_in[7];
    const float* w2l = (const float*)d_in[8];
    const float* b2l = (const float*)d_in[9];
    const float* w2r = (const float*)d_in[10];
    const float* b2r = (const float*)d_in[11];
    const float* att2 = (const float*)d_in[12];
    const float* gb2  = (const float*)d_in[13];
    const float* w3l = (const float*)d_in[14];
    const float* b3l = (const float*)d_in[15];
    const float* w3r = (const float*)d_in[16];
    const float* b3r = (const float*)d_in[17];
    const float* att3 = (const float*)d_in[18];
    const float* gb3  = (const float*)d_in[19];
    const float* dw1 = (const float*)d_in[20];
    const float* db1 = (const float*)d_in[21];
    const float* dw2 = (const float*)d_in[22];
    const float* db2 = (const float*)d_in[23];
    const float* dw3 = (const float*)d_in[24];
    const float* db3 = (const float*)d_in[25];

    void* p;
    cudaGetSymbolAddress(&p, g_xl);   float* xl   = (float*)p;
    cudaGetSymbolAddress(&p, g_xr);   float* xr   = (float*)p;
    cudaGetSymbolAddress(&p, g_buf1); float* buf1 = (float*)p;
    cudaGetSymbolAddress(&p, g_buf2); float* buf2 = (float*)p;
    cudaGetSymbolAddress(&p, g_ah);   h_ah = (__half*)p;
    cudaGetSymbolAddress(&p, g_b0);   h_b0 = (__half*)p;
    cudaGetSymbolAddress(&p, g_b1);   h_b1 = (__half*)p;

    // edges (dtype-robust) + per-layer softmax state init + CSR
    detect_dtype_kernel<<<1, 256>>>(ei);
    build_edges_kernel<<<(3 * NN * HH + 255) / 256, 256>>>(ei);
    csr_rank_kernel<<<(ET + 255) / 256, 256>>>();
    csr_scan_kernel<<<1, NN>>>();
    csr_place_kernel<<<(ET + 255) / 256, 256>>>();

    // ---- GAT layer 1 (Cin=4, fp32 pair GEMM), Cout=128
    sgemm_kernel<<<dim3(32, 8, 2), 256>>>(x, w1l, w1r, b1l, b1r, xl, xr,
                                          NN, HH * 128, 4, 0);
    gat_attention(att1, gb1, buf1, 128, 0, 1);

    // ---- GAT layer 2: Cin=128, Cout=512
    convert_A(buf1, NN, 128, 128);
    run_tc_pair(w2l, b2l, xl, w2r, b2r, xr, NN, HH * 512, 128, 128, 0, 2);
    gat_attention(att2, gb2, buf2, 512, 1, 1);

    // ---- GAT layer 3: Cin=512, Cout=1028
    convert_A(buf2, NN, 512, 512);
    run_tc_pair(w3l, b3l, xl, w3r, b3r, xr, NN, HH * 1028, 512, 512, 0, 2);
    gat_attention(att3, gb3, buf1, 1028, 2, 0);

    // ---- decoder MLP
    convert_A(buf1, NN, 1028, 1088);
    run_tc_pair(dw1, db1, buf2, 0, 0, 0, NN, 512, 1028, 1088, 1, 1);
    convert_A(buf2, NN, 512, 512);
    run_tc_pair(dw2, db2, buf1, 0, 0, 0, NN, 128, 512, 512, 1, 1);
    sgemm_kernel<<<dim3(1, 8, 1), 256>>>(buf1, dw3, dw3, db3, db3,
                                         (float*)d_out, (float*)d_out,
                                         NN, 2, 128, 0);

    (void)in_sizes; (void)n_in; (void)out_size;
}

// round 10
// speedup vs baseline: 4.8180x; 1.1658x over previous
#include <cuda_runtime.h>
#include <cuda_fp16.h>
#include <cstdint>

#define NN   1024      // nodes
#define EE   2048      // raw edges
#define ET   3072      // edges + self loops
#define HH   32        // heads
#define CMX  1028      // max per-head channel dim
#define KPMX 1088      // max padded K
#define BMAX 16842752  // 32896*512 max weight elements

// ---------------- scratch (device globals; no allocation allowed) ----------------
__device__ __half   g_xl[(size_t)NN * HH * CMX];
__device__ __half   g_xr[(size_t)NN * HH * CMX];
__device__ float    g_buf1[NN * CMX];
__device__ float    g_buf2[NN * CMX];
__device__ float    g_score[ET * HH];
__device__ float    g_alpha[ET * HH];
__device__ unsigned g_smax[3 * NN * HH];
__device__ float    g_denom[3 * NN * HH];
__device__ int      g_src[ET];
__device__ int      g_dst[ET];
__device__ int      g_rank[ET];
__device__ int      g_deg[NN];
__device__ int      g_rowptr[NN + 1];
__device__ int      g_eid[ET];
__device__ int      g_is64;
__device__ __half   g_ah[NN * KPMX];
__device__ __half   g_b0[BMAX];
__device__ __half   g_b1[BMAX];

// ---------------- helpers ----------------
__device__ __forceinline__ unsigned flipf(float f) {
    unsigned u = __float_as_uint(f);
    return u ^ ((unsigned)((int)u >> 31) | 0x80000000u);
}
__device__ __forceinline__ float unflipf(unsigned v) {
    unsigned m = (v & 0x80000000u) ? 0x80000000u : 0xFFFFFFFFu;
    return __uint_as_float(v ^ m);
}

// ---------------- edge dtype detection ----------------
__global__ void detect_dtype_kernel(const void* ei) {
    __shared__ int bad;
    if (threadIdx.x == 0) bad = 0;
    __syncthreads();
    const long long* p = (const long long*)ei;
    for (int i = threadIdx.x; i < EE; i += blockDim.x) {
        long long v = p[i];
        if (v < 0 || v >= NN) bad = 1;
    }
    __syncthreads();
    if (threadIdx.x == 0) g_is64 = !bad;
}

// ---------------- edge build + softmax-state init + deg zero ----------------
__global__ void build_edges_kernel(const void* ei) {
    int i = blockIdx.x * blockDim.x + threadIdx.x;
    if (i < ET) {
        if (i < EE) {
            if (g_is64) {
                const long long* p = (const long long*)ei;
                g_src[i] = (int)p[i];
                g_dst[i] = (int)p[EE + i];
            } else {
                const int* p = (const int*)ei;
                g_src[i] = p[i];
                g_dst[i] = p[EE + i];
            }
        } else {
            g_src[i] = i - EE;
            g_dst[i] = i - EE;
        }
    }
    if (i < 3 * NN * HH) {
        g_smax[i] = 0u;
        g_denom[i] = 0.f;
    }
    if (i < NN) g_deg[i] = 0;
}

// ---------------- CSR build (deterministic) ----------------
__global__ void csr_rank_kernel() {
    __shared__ int sd[ET];
    int tid = threadIdx.x;
    for (int i = tid; i < ET; i += blockDim.x) sd[i] = g_dst[i];
    __syncthreads();
    int e = blockIdx.x * blockDim.x + tid;
    if (e < ET) {
        int d = sd[e], r = 0;
        for (int e2 = 0; e2 < e; e2++) r += (sd[e2] == d);
        g_rank[e] = r;
        atomicAdd(&g_deg[d], 1);
    }
}

__global__ void csr_scan_kernel() {
    __shared__ int s[NN];
    int t = threadIdx.x;
    s[t] = g_deg[t];
    __syncthreads();
    for (int o = 1; o < NN; o <<= 1) {
        int v = (t >= o) ? s[t - o] : 0;
        __syncthreads();
        s[t] += v;
        __syncthreads();
    }
    g_rowptr[t + 1] = s[t];
    if (t == 0) g_rowptr[0] = 0;
}

__global__ void csr_place_kernel() {
    int e = blockIdx.x * blockDim.x + threadIdx.x;
    if (e < ET) g_eid[g_rowptr[g_dst[e]] + g_rank[e]] = e;
}

// ---------------- fp32 -> fp16 (A: col pad, float4) ----------------
__global__ void convertA_kernel(const float* __restrict__ src,
                                int M, int K, int Kp) {
    int i4 = blockIdx.x * blockDim.x + threadIdx.x;
    int tot = (M * Kp) >> 2;
    if (i4 >= tot) return;
    int kp4 = Kp >> 2;
    int r = i4 / kp4, c4 = (i4 - r * kp4) << 2;
    float v[4];
    if (c4 + 3 < K) {
        float4 f = *(const float4*)(src + (size_t)r * K + c4);
        v[0] = f.x; v[1] = f.y; v[2] = f.z; v[3] = f.w;
    } else {
#pragma unroll
        for (int j = 0; j < 4; j++)
            v[j] = (c4 + j < K) ? src[(size_t)r * K + c4 + j] : 0.f;
    }
    size_t o = (size_t)r * Kp + c4;
    *(__half2*)(g_ah + o)     = __halves2half2(__float2half_rn(v[0]), __float2half_rn(v[1]));
    *(__half2*)(g_ah + o + 2) = __halves2half2(__float2half_rn(v[2]), __float2half_rn(v[3]));
}

// ---------------- fp32 [K,Nn] -> fp16, row pad to Kp; pair fused via blockIdx.y ----------------
__global__ void convertB_kernel(const float* __restrict__ B0,
                                const float* __restrict__ B1,
                                int K, int Nn, int Kp) {
    int i4 = blockIdx.x * blockDim.x + threadIdx.x;
    int tot = (Kp * Nn) >> 2;
    if (i4 >= tot) return;
    const float* src = blockIdx.y ? B1 : B0;
    __half* dst = blockIdx.y ? g_b1 : g_b0;
    int n4 = Nn >> 2;
    int r = i4 / n4, c4 = (i4 - r * n4) << 2;
    float v[4];
    if (r < K) {
        float4 f = *(const float4*)(src + (size_t)r * Nn + c4);
        v[0] = f.x; v[1] = f.y; v[2] = f.z; v[3] = f.w;
    } else {
        v[0] = v[1] = v[2] = v[3] = 0.f;
    }
    size_t o = (size_t)r * Nn + c4;
    *(__half2*)(dst + o)     = __halves2half2(__float2half_rn(v[0]), __float2half_rn(v[1]));
    *(__half2*)(dst + o + 2) = __halves2half2(__float2half_rn(v[2]), __float2half_rn(v[3]));
}

// ---------------- tensor-core GEMM (plain fp16, fp32 accum, cp.async pipeline) ----------------
// C[M,Nn] = A[M,Kp] @ B[Kp,Nn] + bias, optional leakyrelu(0.01); fp32 or fp16 output.
#define ASTR 40
#define BSTR 136
#define AOFF 0
#define BOFF 10240
#define BUFSZ 18944
#define DSMEM (2 * BUFSZ)

#define LDMX4(R0,R1,R2,R3,ADDR) \
    asm volatile("ldmatrix.sync.aligned.m8n8.x4.shared.b16 {%0,%1,%2,%3}, [%4];" \
        : "=r"(R0), "=r"(R1), "=r"(R2), "=r"(R3) : "r"(ADDR))
#define LDMX2T(R0,R1,ADDR) \
    asm volatile("ldmatrix.sync.aligned.m8n8.x2.trans.shared.b16 {%0,%1}, [%2];" \
        : "=r"(R0), "=r"(R1) : "r"(ADDR))
#define MMA16816(C0,C1,C2,C3,A0,A1,A2,A3,B0,B1) \
    asm volatile("mma.sync.aligned.m16n8k16.row.col.f32.f16.f16.f32 " \
        "{%0,%1,%2,%3}, {%4,%5,%6,%7}, {%8,%9}, {%0,%1,%2,%3};" \
        : "+f"(C0), "+f"(C1), "+f"(C2), "+f"(C3) \
        : "r"(A0), "r"(A1), "r"(A2), "r"(A3), "r"(B0), "r"(B1))
#define CP16(SADDR, GPTR) \
    asm volatile("cp.async.ca.shared.global [%0], [%1], 16;" :: "r"(SADDR), "l"(GPTR))

__global__ __launch_bounds__(256) void tc_gemm_kernel(
    const __half* __restrict__ Ah,
    const __half* __restrict__ B0, const __half* __restrict__ B1,
    const float* __restrict__ bias0, const float* __restrict__ bias1,
    void* __restrict__ C0v, void* __restrict__ C1v,
    int Nn, int Kp, int act, int hout)
{
    extern __shared__ char smem[];
    const uint32_t sbase = (uint32_t)__cvta_generic_to_shared(smem);

    const int tid  = threadIdx.x;
    const int warp = tid >> 5;
    const int lane = tid & 31;
    const int wm = (warp >> 2) * 64;
    const int wn = (warp & 3) * 32;
    const int bx = blockIdx.x * 128;
    const int by = blockIdx.y * 128;
    const int z  = blockIdx.z;

    const __half* B = z ? B1 : B0;
    const float* bias = z ? bias1 : bias0;
    void* Cv = z ? C1v : C0v;

    float acc[4][4][4];
#pragma unroll
    for (int mi = 0; mi < 4; mi++)
#pragma unroll
        for (int ni = 0; ni < 4; ni++)
#pragma unroll
            for (int k = 0; k < 4; k++) acc[mi][ni][k] = 0.f;

    const int nc = Kp >> 5;

    auto load_tile = [&](int c, int b) {
        const int k0 = c << 5;
        const uint32_t base = sbase + b * BUFSZ;
#pragma unroll
        for (int j = 0; j < 2; j++) {
            int idx = tid + j * 256;
            int row = idx >> 2, seg = idx & 3;
            size_t go = (size_t)(by + row) * Kp + k0 + seg * 8;
            uint32_t so = base + (uint32_t)(row * ASTR + seg * 8) * 2;
            CP16(so + AOFF, Ah + go);
        }
#pragma unroll
        for (int j = 0; j < 2; j++) {
            int idx = tid + j * 256;
            int row = idx >> 4, seg = idx & 15;
            size_t go = (size_t)(k0 + row) * Nn + bx + seg * 8;
            uint32_t so = base + (uint32_t)(row * BSTR + seg * 8) * 2;
            CP16(so + BOFF, B + go);
        }
        asm volatile("cp.async.commit_group;" ::: "memory");
    };

    const int r8 = lane & 7;
    const int gA = lane >> 3;
    const int gB = (lane >> 3) & 1;

    load_tile(0, 0);

    for (int c = 0; c < nc; c++) {
        const int b = c & 1;
        if (c + 1 < nc) {
            load_tile(c + 1, (c + 1) & 1);
            asm volatile("cp.async.wait_group 1;" ::: "memory");
        } else {
            asm volatile("cp.async.wait_group 0;" ::: "memory");
        }
        __syncthreads();

        const uint32_t base = sbase + b * BUFSZ;
#pragma unroll
        for (int ks = 0; ks < 2; ks++) {
            const int ko = ks * 16;
            uint32_t ah[4][4], bb[4][2];
#pragma unroll
            for (int mi = 0; mi < 4; mi++) {
                int row = wm + mi * 16 + r8 + (gA & 1) * 8;
                int col = ko + (gA >> 1) * 8;
                uint32_t off = (uint32_t)(row * ASTR + col) * 2;
                LDMX4(ah[mi][0], ah[mi][1], ah[mi][2], ah[mi][3], base + AOFF + off);
            }
#pragma unroll
            for (int ni = 0; ni < 4; ni++) {
                int row = ko + gB * 8 + r8;
                int col = wn + ni * 8;
                uint32_t off = (uint32_t)(row * BSTR + col) * 2;
                LDMX2T(bb[ni][0], bb[ni][1], base + BOFF + off);
            }
#pragma unroll
            for (int mi = 0; mi < 4; mi++) {
#pragma unroll
                for (int ni = 0; ni < 4; ni++) {
                    float* cc = acc[mi][ni];
                    MMA16816(cc[0], cc[1], cc[2], cc[3],
                             ah[mi][0], ah[mi][1], ah[mi][2], ah[mi][3],
                             bb[ni][0], bb[ni][1]);
                }
            }
        }
        __syncthreads();
    }

    const int g = lane >> 2, tig = lane & 3;
#pragma unroll
    for (int mi = 0; mi < 4; mi++) {
#pragma unroll
        for (int ni = 0; ni < 4; ni++) {
            int row = by + wm + mi * 16 + g;
            int col = bx + wn + ni * 8 + tig * 2;
            float bv0 = bias[col], bv1 = bias[col + 1];
            float v0 = acc[mi][ni][0] + bv0;
            float v1 = acc[mi][ni][1] + bv1;
            float v2 = acc[mi][ni][2] + bv0;
            float v3 = acc[mi][ni][3] + bv1;
            if (act) {
                v0 = (v0 > 0.f) ? v0 : 0.01f * v0;
                v1 = (v1 > 0.f) ? v1 : 0.01f * v1;
                v2 = (v2 > 0.f) ? v2 : 0.01f * v2;
                v3 = (v3 > 0.f) ? v3 : 0.01f * v3;
            }
            if (hout) {
                __half* Ch = (__half*)Cv;
                *(__half2*)(Ch + (size_t)row * Nn + col) =
                    __halves2half2(__float2half_rn(v0), __float2half_rn(v1));
                *(__half2*)(Ch + (size_t)(row + 8) * Nn + col) =
                    __halves2half2(__float2half_rn(v2), __float2half_rn(v3));
            } else {
                float* Cf = (float*)Cv;
                Cf[(size_t)row * Nn + col]           = v0;
                Cf[(size_t)row * Nn + col + 1]       = v1;
                Cf[(size_t)(row + 8) * Nn + col]     = v2;
                Cf[(size_t)(row + 8) * Nn + col + 1] = v3;
            }
        }
    }
}

// ---------------- fp32 SGEMM with z-pair fusion; fp32 or fp16 output ----------------
__global__ void sgemm_kernel(const float* __restrict__ A,
                             const float* __restrict__ B0, const float* __restrict__ B1,
                             const float* __restrict__ bias0, const float* __restrict__ bias1,
                             void* __restrict__ C0v, void* __restrict__ C1v,
                             int M, int Nn, int K, int act, int hout) {
    __shared__ float As[8][128];
    __shared__ float Bs[8][128];
    const int bx = blockIdx.x * 128;
    const int by = blockIdx.y * 128;
    const int z  = blockIdx.z;
    const float* B = z ? B1 : B0;
    const float* bias = z ? bias1 : bias0;
    void* Cv = z ? C1v : C0v;
    const int tid = threadIdx.x;
    const int tr = tid / 16;
    const int tc = tid % 16;

    float acc[8][8];
#pragma unroll
    for (int i = 0; i < 8; i++)
#pragma unroll
        for (int j = 0; j < 8; j++) acc[i][j] = 0.f;

    const int row_a = tid / 2;
    const int cola0 = (tid % 2) * 4;
    const int row_b = tid / 32;
    const int colb0 = (tid % 32) * 4;

    for (int k0 = 0; k0 < K; k0 += 8) {
#pragma unroll
        for (int i = 0; i < 4; i++) {
            int r = by + row_a;
            int kk = k0 + cola0 + i;
            As[cola0 + i][row_a] = (r < M && kk < K) ? A[(size_t)r * K + kk] : 0.f;
        }
#pragma unroll
        for (int i = 0; i < 4; i++) {
            int kk = k0 + row_b;
            int c = bx + colb0 + i;
            Bs[row_b][colb0 + i] = (kk < K && c < Nn) ? B[(size_t)kk * Nn + c] : 0.f;
        }
        __syncthreads();
#pragma unroll
        for (int kk = 0; kk < 8; kk++) {
            float a[8], b[8];
#pragma unroll
            for (int i = 0; i < 8; i++) a[i] = As[kk][tr + 16 * i];
#pragma unroll
            for (int j = 0; j < 8; j++) b[j] = Bs[kk][tc + 16 * j];
#pragma unroll
            for (int i = 0; i < 8; i++)
#pragma unroll
                for (int j = 0; j < 8; j++) acc[i][j] += a[i] * b[j];
        }
        __syncthreads();
    }

#pragma unroll
    for (int i = 0; i < 8; i++) {
        int r = by + tr + 16 * i;
        if (r >= M) continue;
#pragma unroll
        for (int j = 0; j < 8; j++) {
            int c = bx + tc + 16 * j;
            if (c >= Nn) continue;
            float v = acc[i][j] + bias[c];
            if (act) v = (v > 0.f) ? v : 0.01f * v;
            if (hout) ((__half*)Cv)[(size_t)r * Nn + c] = __float2half_rn(v);
            else      ((float*)Cv)[(size_t)r * Nn + c] = v;
        }
    }
}

// ---------------- per-(edge,head) attention score (fp16 inputs, uint2 loads) ----------------
__global__ void score_kernel(const float* __restrict__ att, int C, int L) {
    int gw = (blockIdx.x * blockDim.x + threadIdx.x) >> 5;
    int lane = threadIdx.x & 31;
    if (gw >= ET * HH) return;
    int e = gw / HH, h = gw % HH;
    int s = g_src[e], d = g_dst[e];
    const int n4 = C >> 2;
    const uint2* xl = (const uint2*)(g_xl + ((size_t)s * HH + h) * C);
    const uint2* xr = (const uint2*)(g_xr + ((size_t)d * HH + h) * C);
    const float4* at = (const float4*)(att + h * C);
    float acc = 0.f;
    for (int c = lane; c < n4; c += 32) {
        uint2 ua = xl[c], ub = xr[c];
        float2 a0 = __half22float2(*(__half2*)&ua.x);
        float2 a1 = __half22float2(*(__half2*)&ua.y);
        float2 b0 = __half22float2(*(__half2*)&ub.x);
        float2 b1 = __half22float2(*(__half2*)&ub.y);
        float4 w = at[c];
        float v0 = a0.x + b0.x, v1 = a0.y + b0.y;
        float v2 = a1.x + b1.x, v3 = a1.y + b1.y;
        v0 = (v0 > 0.f) ? v0 : 0.2f * v0;
        v1 = (v1 > 0.f) ? v1 : 0.2f * v1;
        v2 = (v2 > 0.f) ? v2 : 0.2f * v2;
        v3 = (v3 > 0.f) ? v3 : 0.2f * v3;
        acc += w.x * v0 + w.y * v1 + w.z * v2 + w.w * v3;
    }
#pragma unroll
    for (int o = 16; o; o >>= 1) acc += __shfl_xor_sync(0xffffffffu, acc, o);
    if (lane == 0) {
        g_score[e * HH + h] = acc;
        atomicMax(&g_smax[L * NN * HH + d * HH + h], flipf(acc));
    }
}

// ---------------- alpha = exp(score - max); accumulate denominators ----------------
__global__ void alpha_kernel(int L) {
    int i = blockIdx.x * blockDim.x + threadIdx.x;
    if (i >= ET * HH) return;
    int e = i / HH, h = i % HH;
    int d = g_dst[e];
    float m = unflipf(g_smax[L * NN * HH + d * HH + h]);
    float a = expf(g_score[i] - m);
    g_alpha[i] = a;
    atomicAdd(&g_denom[L * NN * HH + d * HH + h], a);
}

// ---------------- CSR aggregation (fp16 x) + bias + optional lrelu; no atomics ----------------
__global__ void aggregate_kernel(const float* __restrict__ bias,
                                 float* __restrict__ out, int C, int L, int act) {
    const int n = blockIdx.x;
    const int c = blockIdx.y * 128 + threadIdx.x;
    const int tid = threadIdx.x;
    __shared__ float sw[64 * HH];
    __shared__ int   sid[64];
    const int r0 = g_rowptr[n], r1 = g_rowptr[n + 1];
    const float* dnm = g_denom + L * NN * HH + n * HH;
    float acc = 0.f;
    for (int r = r0; r < r1; r += 64) {
        int cd = min(64, r1 - r);
        __syncthreads();
        for (int i = tid; i < cd * HH; i += 128) {
            int le = i >> 5, h = i & 31;
            int e = g_eid[r + le];
            sw[i] = g_alpha[e * HH + h] / dnm[h] * (1.0f / HH);
        }
        if (tid < cd) sid[tid] = g_src[g_eid[r + tid]];
        __syncthreads();
        if (c < C) {
            for (int le = 0; le < cd; le++) {
                const __half* xrow = g_xl + (size_t)sid[le] * HH * C + c;
                const float* wrow = sw + le * HH;
#pragma unroll 4
                for (int h = 0; h < HH; h++)
                    acc += wrow[h] * __half2float(xrow[(size_t)h * C]);
            }
        }
    }
    if (c < C) {
        float v = acc + bias[c];
        if (act) v = (v > 0.f) ? v : 0.01f * v;
        out[(size_t)n * C + c] = v;
    }
}

// ---------------- host-side orchestration ----------------
static __half *h_ah, *h_b0, *h_b1;

static void convert_A(const float* A, int M, int K, int Kp) {
    int n4 = (M * Kp) >> 2;
    convertA_kernel<<<(n4 + 255) / 256, 256>>>(A, M, K, Kp);
}

static void run_tc_pair(const float* B0, const float* bias0, void* C0,
                        const float* B1, const float* bias1, void* C1,
                        int M, int Nn, int K, int Kp, int act, int nz, int hout) {
    int n4 = (Kp * Nn) >> 2;
    convertB_kernel<<<dim3((n4 + 255) / 256, nz), 256>>>(B0, B1 ? B1 : B0, K, Nn, Kp);
    cudaFuncSetAttribute(tc_gemm_kernel, cudaFuncAttributeMaxDynamicSharedMemorySize, DSMEM);
    dim3 grid(Nn / 128, M / 128, nz);
    tc_gemm_kernel<<<grid, 256, DSMEM>>>(h_ah, h_b0, h_b1,
                                         bias0, bias1 ? bias1 : bias0,
                                         C0, C1 ? C1 : C0, Nn, Kp, act, hout);
}

static void gat_attention(const float* att, const float* gb, float* zout,
                          int Cout, int L, int act_after) {
    score_kernel<<<(ET * HH) / 8, 256>>>(att, Cout, L);
    alpha_kernel<<<(ET * HH + 255) / 256, 256>>>(L);
    aggregate_kernel<<<dim3(NN, (Cout + 127) / 128), 128>>>(gb, zout, Cout, L, act_after);
}

extern "C" void kernel_launch(void* const* d_in, const int* in_sizes, int n_in,
                              void* d_out, int out_size) {
    const float* x  = (const float*)d_in[0];
    const void*  ei = d_in[1];
    const float* w1l = (const float*)d_in[2];
    const float* b1l = (const float*)d_in[3];
    const float* w1r = (const float*)d_in[4];
    const float* b1r = (const float*)d_in[5];
    const float* att1 = (const float*)d_in[6];
    const float* gb1  = (const float*)d_in[7];
    const float* w2l = (const float*)d_in[8];
    const float* b2l = (const float*)d_in[9];
    const float* w2r = (const float*)d_in[10];
    const float* b2r = (const float*)d_in[11];
    const float* att2 = (const float*)d_in[12];
    const float* gb2  = (const float*)d_in[13];
    const float* w3l = (const float*)d_in[14];
    const float* b3l = (const float*)d_in[15];
    const float* w3r = (const float*)d_in[16];
    const float* b3r = (const float*)d_in[17];
    const float* att3 = (const float*)d_in[18];
    const float* gb3  = (const float*)d_in[19];
    const float* dw1 = (const float*)d_in[20];
    const float* db1 = (const float*)d_in[21];
    const float* dw2 = (const float*)d_in[22];
    const float* db2 = (const float*)d_in[23];
    const float* dw3 = (const float*)d_in[24];
    const float* db3 = (const float*)d_in[25];

    void* p;
    cudaGetSymbolAddress(&p, g_xl);   __half* xl = (__half*)p;
    cudaGetSymbolAddress(&p, g_xr);   __half* xr = (__half*)p;
    cudaGetSymbolAddress(&p, g_buf1); float* buf1 = (float*)p;
    cudaGetSymbolAddress(&p, g_buf2); float* buf2 = (float*)p;
    cudaGetSymbolAddress(&p, g_ah);   h_ah = (__half*)p;
    cudaGetSymbolAddress(&p, g_b0);   h_b0 = (__half*)p;
    cudaGetSymbolAddress(&p, g_b1);   h_b1 = (__half*)p;

    // edges (dtype-robust) + per-layer softmax state init + CSR
    detect_dtype_kernel<<<1, 256>>>(ei);
    build_edges_kernel<<<(3 * NN * HH + 255) / 256, 256>>>(ei);
    csr_rank_kernel<<<(ET + 255) / 256, 256>>>();
    csr_scan_kernel<<<1, NN>>>();
    csr_place_kernel<<<(ET + 255) / 256, 256>>>();

    // ---- GAT layer 1 (Cin=4, fp32 pair GEMM, fp16 out), Cout=128
    sgemm_kernel<<<dim3(32, 8, 2), 256>>>(x, w1l, w1r, b1l, b1r, xl, xr,
                                          NN, HH * 128, 4, 0, 1);
    gat_attention(att1, gb1, buf1, 128, 0, 1);

    // ---- GAT layer 2: Cin=128, Cout=512
    convert_A(buf1, NN, 128, 128);
    run_tc_pair(w2l, b2l, xl, w2r, b2r, xr, NN, HH * 512, 128, 128, 0, 2, 1);
    gat_attention(att2, gb2, buf2, 512, 1, 1);

    // ---- GAT layer 3: Cin=512, Cout=1028
    convert_A(buf2, NN, 512, 512);
    run_tc_pair(w3l, b3l, xl, w3r, b3r, xr, NN, HH * 1028, 512, 512, 0, 2, 1);
    gat_attention(att3, gb3, buf1, 1028, 2, 0);

    // ---- decoder MLP (fp32 outputs)
    convert_A(buf1, NN, 1028, 1088);
    run_tc_pair(dw1, db1, buf2, 0, 0, 0, NN, 512, 1028, 1088, 1, 1, 0);
    convert_A(buf2, NN, 512, 512);
    run_tc_pair(dw2, db2, buf1, 0, 0, 0, NN, 128, 512, 512, 1, 1, 0);
    sgemm_kernel<<<dim3(1, 8, 1), 256>>>(buf1, dw3, dw3, db3, db3,
                                         d_out, d_out, NN, 2, 128, 0, 0);

    (void)in_sizes; (void)n_in; (void)out_size;
}

// round 12
// speedup vs baseline: 4.9861x; 1.0349x over previous
#include <cuda_runtime.h>
#include <cuda_fp16.h>
#include <cstdint>

#define NN   1024      // nodes
#define EE   2048      // raw edges
#define ET   3072      // edges + self loops
#define HH   32        // heads
#define CMX  1028      // max per-head channel dim
#define KPMX 1088      // max padded K
#define BMAX 16842752  // 32896*512 max weight elements

// ---------------- scratch (device globals; no allocation allowed) ----------------
__device__ __half   g_xl[(size_t)NN * HH * CMX];
__device__ __half   g_xr[(size_t)NN * HH * CMX];
__device__ float    g_score[ET * HH];
__device__ float    g_alpha[ET * HH];
__device__ unsigned g_smax[3 * NN * HH];
__device__ float    g_denom[3 * NN * HH];
__device__ int      g_src[ET];
__device__ int      g_dst[ET];
__device__ int      g_rank[ET];
__device__ int      g_deg[NN];
__device__ int      g_rowptr[NN + 1];
__device__ int      g_eid[ET];
__device__ int      g_is64;
__device__ __half   g_ah[NN * KPMX];
__device__ __half   g_b0[BMAX];
__device__ __half   g_b1[BMAX];

// ---------------- helpers ----------------
__device__ __forceinline__ unsigned flipf(float f) {
    unsigned u = __float_as_uint(f);
    return u ^ ((unsigned)((int)u >> 31) | 0x80000000u);
}
__device__ __forceinline__ float unflipf(unsigned v) {
    unsigned m = (v & 0x80000000u) ? 0x80000000u : 0xFFFFFFFFu;
    return __uint_as_float(v ^ m);
}

// ---------------- edge dtype detection ----------------
__global__ void detect_dtype_kernel(const void* ei) {
    __shared__ int bad;
    if (threadIdx.x == 0) bad = 0;
    __syncthreads();
    const long long* p = (const long long*)ei;
    for (int i = threadIdx.x; i < EE; i += blockDim.x) {
        long long v = p[i];
        if (v < 0 || v >= NN) bad = 1;
    }
    __syncthreads();
    if (threadIdx.x == 0) g_is64 = !bad;
}

// ---------------- edge build + softmax-state init + deg zero ----------------
__global__ void build_edges_kernel(const void* ei) {
    int i = blockIdx.x * blockDim.x + threadIdx.x;
    if (i < ET) {
        if (i < EE) {
            if (g_is64) {
                const long long* p = (const long long*)ei;
                g_src[i] = (int)p[i];
                g_dst[i] = (int)p[EE + i];
            } else {
                const int* p = (const int*)ei;
                g_src[i] = p[i];
                g_dst[i] = p[EE + i];
            }
        } else {
            g_src[i] = i - EE;
            g_dst[i] = i - EE;
        }
    }
    if (i < 3 * NN * HH) {
        g_smax[i] = 0u;
        g_denom[i] = 0.f;
    }
    if (i < NN) g_deg[i] = 0;
}

// ---------------- CSR build (deterministic) ----------------
__global__ void csr_rank_kernel() {
    __shared__ int sd[ET];
    int tid = threadIdx.x;
    for (int i = tid; i < ET; i += blockDim.x) sd[i] = g_dst[i];
    __syncthreads();
    int e = blockIdx.x * blockDim.x + tid;
    if (e < ET) {
        int d = sd[e], r = 0;
        for (int e2 = 0; e2 < e; e2++) r += (sd[e2] == d);
        g_rank[e] = r;
        atomicAdd(&g_deg[d], 1);
    }
}

// scan + place fused: single block of NN threads
__global__ void csr_scan_place_kernel() {
    __shared__ int s[NN];
    __shared__ int start[NN];
    int t = threadIdx.x;
    s[t] = g_deg[t];
    __syncthreads();
    for (int o = 1; o < NN; o <<= 1) {
        int v = (t >= o) ? s[t - o] : 0;
        __syncthreads();
        s[t] += v;
        __syncthreads();
    }
    g_rowptr[t + 1] = s[t];
    start[t] = s[t] - g_deg[t];
    if (t == 0) g_rowptr[0] = 0;
    __syncthreads();
    for (int e = t; e < ET; e += NN)
        g_eid[start[g_dst[e]] + g_rank[e]] = e;
}

// ---------------- fp32 [K,Nn] -> fp16, row pad to Kp; pair fused via blockIdx.y ----------------
__global__ void convertB_kernel(const float* __restrict__ B0,
                                const float* __restrict__ B1,
                                int K, int Nn, int Kp) {
    int i4 = blockIdx.x * blockDim.x + threadIdx.x;
    int tot = (Kp * Nn) >> 2;
    if (i4 >= tot) return;
    const float* src = blockIdx.y ? B1 : B0;
    __half* dst = blockIdx.y ? g_b1 : g_b0;
    int n4 = Nn >> 2;
    int r = i4 / n4, c4 = (i4 - r * n4) << 2;
    float v[4];
    if (r < K) {
        float4 f = *(const float4*)(src + (size_t)r * Nn + c4);
        v[0] = f.x; v[1] = f.y; v[2] = f.z; v[3] = f.w;
    } else {
        v[0] = v[1] = v[2] = v[3] = 0.f;
    }
    size_t o = (size_t)r * Nn + c4;
    *(__half2*)(dst + o)     = __halves2half2(__float2half_rn(v[0]), __float2half_rn(v[1]));
    *(__half2*)(dst + o + 2) = __halves2half2(__float2half_rn(v[2]), __float2half_rn(v[3]));
}

// ---------------- tensor-core GEMM (plain fp16, fp32 accum, cp.async pipeline) ----------------
// C[M,Nn] = A[M,Kp] @ B[Kp,Nn] + bias, optional leakyrelu(0.01); fp32 or fp16 output.
#define ASTR 40
#define BSTR 136
#define AOFF 0
#define BOFF 10240
#define BUFSZ 18944
#define DSMEM (2 * BUFSZ)

#define LDMX4(R0,R1,R2,R3,ADDR) \
    asm volatile("ldmatrix.sync.aligned.m8n8.x4.shared.b16 {%0,%1,%2,%3}, [%4];" \
        : "=r"(R0), "=r"(R1), "=r"(R2), "=r"(R3) : "r"(ADDR))
#define LDMX2T(R0,R1,ADDR) \
    asm volatile("ldmatrix.sync.aligned.m8n8.x2.trans.shared.b16 {%0,%1}, [%2];" \
        : "=r"(R0), "=r"(R1) : "r"(ADDR))
#define MMA16816(C0,C1,C2,C3,A0,A1,A2,A3,B0,B1) \
    asm volatile("mma.sync.aligned.m16n8k16.row.col.f32.f16.f16.f32 " \
        "{%0,%1,%2,%3}, {%4,%5,%6,%7}, {%8,%9}, {%0,%1,%2,%3};" \
        : "+f"(C0), "+f"(C1), "+f"(C2), "+f"(C3) \
        : "r"(A0), "r"(A1), "r"(A2), "r"(A3), "r"(B0), "r"(B1))
#define CP16(SADDR, GPTR) \
    asm volatile("cp.async.ca.shared.global [%0], [%1], 16;" :: "r"(SADDR), "l"(GPTR))

__global__ __launch_bounds__(256) void tc_gemm_kernel(
    const __half* __restrict__ Ah,
    const __half* __restrict__ B0, const __half* __restrict__ B1,
    const float* __restrict__ bias0, const float* __restrict__ bias1,
    void* __restrict__ C0v, void* __restrict__ C1v,
    int Nn, int Kp, int act, int hout)
{
    extern __shared__ char smem[];
    const uint32_t sbase = (uint32_t)__cvta_generic_to_shared(smem);

    const int tid  = threadIdx.x;
    const int warp = tid >> 5;
    const int lane = tid & 31;
    const int wm = (warp >> 2) * 64;
    const int wn = (warp & 3) * 32;
    const int bx = blockIdx.x * 128;
    const int by = blockIdx.y * 128;
    const int z  = blockIdx.z;

    const __half* B = z ? B1 : B0;
    const float* bias = z ? bias1 : bias0;
    void* Cv = z ? C1v : C0v;

    float acc[4][4][4];
#pragma unroll
    for (int mi = 0; mi < 4; mi++)
#pragma unroll
        for (int ni = 0; ni < 4; ni++)
#pragma unroll
            for (int k = 0; k < 4; k++) acc[mi][ni][k] = 0.f;

    const int nc = Kp >> 5;

    auto load_tile = [&](int c, int b) {
        const int k0 = c << 5;
        const uint32_t base = sbase + b * BUFSZ;
#pragma unroll
        for (int j = 0; j < 2; j++) {
            int idx = tid + j * 256;
            int row = idx >> 2, seg = idx & 3;
            size_t go = (size_t)(by + row) * Kp + k0 + seg * 8;
            uint32_t so = base + (uint32_t)(row * ASTR + seg * 8) * 2;
            CP16(so + AOFF, Ah + go);
        }
#pragma unroll
        for (int j = 0; j < 2; j++) {
            int idx = tid + j * 256;
            int row = idx >> 4, seg = idx & 15;
            size_t go = (size_t)(k0 + row) * Nn + bx + seg * 8;
            uint32_t so = base + (uint32_t)(row * BSTR + seg * 8) * 2;
            CP16(so + BOFF, B + go);
        }
        asm volatile("cp.async.commit_group;" ::: "memory");
    };

    const int r8 = lane & 7;
    const int gA = lane >> 3;
    const int gB = (lane >> 3) & 1;

    load_tile(0, 0);

    for (int c = 0; c < nc; c++) {
        const int b = c & 1;
        if (c + 1 < nc) {
            load_tile(c + 1, (c + 1) & 1);
            asm volatile("cp.async.wait_group 1;" ::: "memory");
        } else {
            asm volatile("cp.async.wait_group 0;" ::: "memory");
        }
        __syncthreads();

        const uint32_t base = sbase + b * BUFSZ;
#pragma unroll
        for (int ks = 0; ks < 2; ks++) {
            const int ko = ks * 16;
            uint32_t ah[4][4], bb[4][2];
#pragma unroll
            for (int mi = 0; mi < 4; mi++) {
                int row = wm + mi * 16 + r8 + (gA & 1) * 8;
                int col = ko + (gA >> 1) * 8;
                uint32_t off = (uint32_t)(row * ASTR + col) * 2;
                LDMX4(ah[mi][0], ah[mi][1], ah[mi][2], ah[mi][3], base + AOFF + off);
            }
#pragma unroll
            for (int ni = 0; ni < 4; ni++) {
                int row = ko + gB * 8 + r8;
                int col = wn + ni * 8;
                uint32_t off = (uint32_t)(row * BSTR + col) * 2;
                LDMX2T(bb[ni][0], bb[ni][1], base + BOFF + off);
            }
#pragma unroll
            for (int mi = 0; mi < 4; mi++) {
#pragma unroll
                for (int ni = 0; ni < 4; ni++) {
                    float* cc = acc[mi][ni];
                    MMA16816(cc[0], cc[1], cc[2], cc[3],
                             ah[mi][0], ah[mi][1], ah[mi][2], ah[mi][3],
                             bb[ni][0], bb[ni][1]);
                }
            }
        }
        __syncthreads();
    }

    const int g = lane >> 2, tig = lane & 3;
#pragma unroll
    for (int mi = 0; mi < 4; mi++) {
#pragma unroll
        for (int ni = 0; ni < 4; ni++) {
            int row = by + wm + mi * 16 + g;
            int col = bx + wn + ni * 8 + tig * 2;
            float bv0 = bias[col], bv1 = bias[col + 1];
            float v0 = acc[mi][ni][0] + bv0;
            float v1 = acc[mi][ni][1] + bv1;
            float v2 = acc[mi][ni][2] + bv0;
            float v3 = acc[mi][ni][3] + bv1;
            if (act) {
                v0 = (v0 > 0.f) ? v0 : 0.01f * v0;
                v1 = (v1 > 0.f) ? v1 : 0.01f * v1;
                v2 = (v2 > 0.f) ? v2 : 0.01f * v2;
                v3 = (v3 > 0.f) ? v3 : 0.01f * v3;
            }
            if (hout) {
                __half* Ch = (__half*)Cv;
                *(__half2*)(Ch + (size_t)row * Nn + col) =
                    __halves2half2(__float2half_rn(v0), __float2half_rn(v1));
                *(__half2*)(Ch + (size_t)(row + 8) * Nn + col) =
                    __halves2half2(__float2half_rn(v2), __float2half_rn(v3));
            } else {
                float* Cf = (float*)Cv;
                Cf[(size_t)row * Nn + col]           = v0;
                Cf[(size_t)row * Nn + col + 1]       = v1;
                Cf[(size_t)(row + 8) * Nn + col]     = v2;
                Cf[(size_t)(row + 8) * Nn + col + 1] = v3;
            }
        }
    }
}

// ---------------- fp32/fp16-A SGEMM with z-pair fusion; fp32 or fp16 output ----------------
__global__ void sgemm_kernel(const void* __restrict__ Av,
                             const float* __restrict__ B0, const float* __restrict__ B1,
                             const float* __restrict__ bias0, const float* __restrict__ bias1,
                             void* __restrict__ C0v, void* __restrict__ C1v,
                             int M, int Nn, int K, int act, int hout, int ahalf) {
    __shared__ float As[8][128];
    __shared__ float Bs[8][128];
    const int bx = blockIdx.x * 128;
    const int by = blockIdx.y * 128;
    const int z  = blockIdx.z;
    const float* B = z ? B1 : B0;
    const float* bias = z ? bias1 : bias0;
    void* Cv = z ? C1v : C0v;
    const int tid = threadIdx.x;
    const int tr = tid / 16;
    const int tc = tid % 16;

    float acc[8][8];
#pragma unroll
    for (int i = 0; i < 8; i++)
#pragma unroll
        for (int j = 0; j < 8; j++) acc[i][j] = 0.f;

    const int row_a = tid / 2;
    const int cola0 = (tid % 2) * 4;
    const int row_b = tid / 32;
    const int colb0 = (tid % 32) * 4;

    for (int k0 = 0; k0 < K; k0 += 8) {
#pragma unroll
        for (int i = 0; i < 4; i++) {
            int r = by + row_a;
            int kk = k0 + cola0 + i;
            float av = 0.f;
            if (r < M && kk < K) {
                av = ahalf ? __half2float(((const __half*)Av)[(size_t)r * K + kk])
                           : ((const float*)Av)[(size_t)r * K + kk];
            }
            As[cola0 + i][row_a] = av;
        }
#pragma unroll
        for (int i = 0; i < 4; i++) {
            int kk = k0 + row_b;
            int c = bx + colb0 + i;
            Bs[row_b][colb0 + i] = (kk < K && c < Nn) ? B[(size_t)kk * Nn + c] : 0.f;
        }
        __syncthreads();
#pragma unroll
        for (int kk = 0; kk < 8; kk++) {
            float a[8], b[8];
#pragma unroll
            for (int i = 0; i < 8; i++) a[i] = As[kk][tr + 16 * i];
#pragma unroll
            for (int j = 0; j < 8; j++) b[j] = Bs[kk][tc + 16 * j];
#pragma unroll
            for (int i = 0; i < 8; i++)
#pragma unroll
                for (int j = 0; j < 8; j++) acc[i][j] += a[i] * b[j];
        }
        __syncthreads();
    }

#pragma unroll
    for (int i = 0; i < 8; i++) {
        int r = by + tr + 16 * i;
        if (r >= M) continue;
#pragma unroll
        for (int j = 0; j < 8; j++) {
            int c = bx + tc + 16 * j;
            if (c >= Nn) continue;
            float v = acc[i][j] + bias[c];
            if (act) v = (v > 0.f) ? v : 0.01f * v;
            if (hout) ((__half*)Cv)[(size_t)r * Nn + c] = __float2half_rn(v);
            else      ((float*)Cv)[(size_t)r * Nn + c] = v;
        }
    }
}

// ---------------- per-(edge,head) attention score (fp16 inputs, uint2 loads) ----------------
__global__ void score_kernel(const float* __restrict__ att, int C, int L) {
    int gw = (blockIdx.x * blockDim.x + threadIdx.x) >> 5;
    int lane = threadIdx.x & 31;
    if (gw >= ET * HH) return;
    int e = gw / HH, h = gw % HH;
    int s = g_src[e], d = g_dst[e];
    const int n4 = C >> 2;
    const uint2* xl = (const uint2*)(g_xl + ((size_t)s * HH + h) * C);
    const uint2* xr = (const uint2*)(g_xr + ((size_t)d * HH + h) * C);
    const float4* at = (const float4*)(att + h * C);
    float acc = 0.f;
    for (int c = lane; c < n4; c += 32) {
        uint2 ua = xl[c], ub = xr[c];
        float2 a0 = __half22float2(*(__half2*)&ua.x);
        float2 a1 = __half22float2(*(__half2*)&ua.y);
        float2 b0 = __half22float2(*(__half2*)&ub.x);
        float2 b1 = __half22float2(*(__half2*)&ub.y);
        float4 w = at[c];
        float v0 = a0.x + b0.x, v1 = a0.y + b0.y;
        float v2 = a1.x + b1.x, v3 = a1.y + b1.y;
        v0 = (v0 > 0.f) ? v0 : 0.2f * v0;
        v1 = (v1 > 0.f) ? v1 : 0.2f * v1;
        v2 = (v2 > 0.f) ? v2 : 0.2f * v2;
        v3 = (v3 > 0.f) ? v3 : 0.2f * v3;
        acc += w.x * v0 + w.y * v1 + w.z * v2 + w.w * v3;
    }
#pragma unroll
    for (int o = 16; o; o >>= 1) acc += __shfl_xor_sync(0xffffffffu, acc, o);
    if (lane == 0) {
        g_score[e * HH + h] = acc;
        atomicMax(&g_smax[L * NN * HH + d * HH + h], flipf(acc));
    }
}

// ---------------- alpha = exp(score - max); accumulate denominators ----------------
__global__ void alpha_kernel(int L) {
    int i = blockIdx.x * blockDim.x + threadIdx.x;
    if (i >= ET * HH) return;
    int e = i / HH, h = i % HH;
    int d = g_dst[e];
    float m = unflipf(g_smax[L * NN * HH + d * HH + h]);
    float a = expf(g_score[i] - m);
    g_alpha[i] = a;
    atomicAdd(&g_denom[L * NN * HH + d * HH + h], a);
}

// ---------------- CSR aggregation (fp16 x) + bias + optional lrelu -> fp16 g_ah [NN,Kp] ----------------
__global__ void aggregate_kernel(const float* __restrict__ bias,
                                 __half* __restrict__ out, int C, int Kp, int L, int act) {
    const int n = blockIdx.x;
    const int c = blockIdx.y * 128 + threadIdx.x;
    const int tid = threadIdx.x;
    __shared__ float sw[64 * HH];
    __shared__ int   sid[64];
    const int r0 = g_rowptr[n], r1 = g_rowptr[n + 1];
    const float* dnm = g_denom + L * NN * HH + n * HH;
    float acc = 0.f;
    for (int r = r0; r < r1; r += 64) {
        int cd = min(64, r1 - r);
        __syncthreads();
        for (int i = tid; i < cd * HH; i += 128) {
            int le = i >> 5, h = i & 31;
            int e = g_eid[r + le];
            sw[i] = g_alpha[e * HH + h] / dnm[h] * (1.0f / HH);
        }
        if (tid < cd) sid[tid] = g_src[g_eid[r + tid]];
        __syncthreads();
        if (c < C) {
            for (int le = 0; le < cd; le++) {
                const __half* xrow = g_xl + (size_t)sid[le] * HH * C + c;
                const float* wrow = sw + le * HH;
#pragma unroll 4
                for (int h = 0; h < HH; h++)
                    acc += wrow[h] * __half2float(xrow[(size_t)h * C]);
            }
        }
    }
    if (c < Kp) {
        float v = 0.f;
        if (c < C) {
            v = acc + bias[c];
            if (act) v = (v > 0.f) ? v : 0.01f * v;
        }
        out[(size_t)n * Kp + c] = __float2half_rn(v);
    }
}

// ---------------- host-side orchestration ----------------
static __half *h_ah, *h_b0, *h_b1;

static void run_tc_pair(const float* B0, const float* bias0, void* C0,
                        const float* B1, const float* bias1, void* C1,
                        int M, int Nn, int K, int Kp, int act, int nz, int hout) {
    int n4 = (Kp * Nn) >> 2;
    convertB_kernel<<<dim3((n4 + 255) / 256, nz), 256>>>(B0, B1 ? B1 : B0, K, Nn, Kp);
    cudaFuncSetAttribute(tc_gemm_kernel, cudaFuncAttributeMaxDynamicSharedMemorySize, DSMEM);
    dim3 grid(Nn / 128, M / 128, nz);
    tc_gemm_kernel<<<grid, 256, DSMEM>>>(h_ah, h_b0, h_b1,
                                         bias0, bias1 ? bias1 : bias0,
                                         C0, C1 ? C1 : C0, Nn, Kp, act, hout);
}

// aggregation writes fp16 directly into g_ah [NN, Kp]
static void gat_attention(const float* att, const float* gb,
                          int Cout, int Kp, int L, int act_after) {
    score_kernel<<<(ET * HH) / 8, 256>>>(att, Cout, L);
    alpha_kernel<<<(ET * HH + 255) / 256, 256>>>(L);
    aggregate_kernel<<<dim3(NN, (Kp + 127) / 128), 128>>>(gb, h_ah, Cout, Kp, L, act_after);
}

extern "C" void kernel_launch(void* const* d_in, const int* in_sizes, int n_in,
                              void* d_out, int out_size) {
    const float* x  = (const float*)d_in[0];
    const void*  ei = d_in[1];
    const float* w1l = (const float*)d_in[2];
    const float* b1l = (const float*)d_in[3];
    const float* w1r = (const float*)d_in[4];
    const float* b1r = (const float*)d_in[5];
    const float* att1 = (const float*)d_in[6];
    const float* gb1  = (const float*)d_in[7];
    const float* w2l = (const float*)d_in[8];
    const float* b2l = (const float*)d_in[9];
    const float* w2r = (const float*)d_in[10];
    const float* b2r = (const float*)d_in[11];
    const float* att2 = (const float*)d_in[12];
    const float* gb2  = (const float*)d_in[13];
    const float* w3l = (const float*)d_in[14];
    const float* b3l = (const float*)d_in[15];
    const float* w3r = (const float*)d_in[16];
    const float* b3r = (const float*)d_in[17];
    const float* att3 = (const float*)d_in[18];
    const float* gb3  = (const float*)d_in[19];
    const float* dw1 = (const float*)d_in[20];
    const float* db1 = (const float*)d_in[21];
    const float* dw2 = (const float*)d_in[22];
    const float* db2 = (const float*)d_in[23];
    const float* dw3 = (const float*)d_in[24];
    const float* db3 = (const float*)d_in[25];

    void* p;
    cudaGetSymbolAddress(&p, g_xl);   __half* xl = (__half*)p;
    cudaGetSymbolAddress(&p, g_xr);   __half* xr = (__half*)p;
    cudaGetSymbolAddress(&p, g_ah);   h_ah = (__half*)p;
    cudaGetSymbolAddress(&p, g_b0);   h_b0 = (__half*)p;
    cudaGetSymbolAddress(&p, g_b1);   h_b1 = (__half*)p;

    // edges (dtype-robust) + per-layer softmax state init + CSR
    detect_dtype_kernel<<<1, 256>>>(ei);
    build_edges_kernel<<<(3 * NN * HH + 255) / 256, 256>>>(ei);
    csr_rank_kernel<<<(ET + 255) / 256, 256>>>();
    csr_scan_place_kernel<<<1, NN>>>();

    // ---- GAT layer 1 (Cin=4, fp32 pair GEMM, fp16 out), Cout=128
    sgemm_kernel<<<dim3(32, 8, 2), 256>>>(x, w1l, w1r, b1l, b1r, xl, xr,
                                          NN, HH * 128, 4, 0, 1, 0);
    gat_attention(att1, gb1, 128, 128, 0, 1);       // -> g_ah [1024,128] fp16

    // ---- GAT layer 2: Cin=128 (Kp=128), Cout=512
    run_tc_pair(w2l, b2l, xl, w2r, b2r, xr, NN, HH * 512, 128, 128, 0, 2, 1);
    gat_attention(att2, gb2, 512, 512, 1, 1);       // -> g_ah [1024,512] fp16

    // ---- GAT layer 3: Cin=512 (Kp=512), Cout=1028
    run_tc_pair(w3l, b3l, xl, w3r, b3r, xr, NN, HH * 1028, 512, 512, 0, 2, 1);
    gat_attention(att3, gb3, 1028, 1088, 2, 0);     // -> g_ah [1024,1088] fp16 (padded)

    // ---- decoder MLP: GEMMs write fp16 A for the next stage directly
    run_tc_pair(dw1, db1, h_ah, 0, 0, 0, NN, 512, 1028, 1088, 1, 1, 1);  // -> g_ah [1024,512]
    run_tc_pair(dw2, db2, h_ah, 0, 0, 0, NN, 128, 512, 512, 1, 1, 1);    // -> g_ah [1024,128]
    sgemm_kernel<<<dim3(1, 8, 1), 256>>>(h_ah, dw3, dw3, db3, db3,
                                         d_out, d_out, NN, 2, 128, 0, 0, 1);

    (void)in_sizes; (void)n_in; (void)out_size;
}